// round 14
// baseline (speedup 1.0000x reference)
#include <cuda_runtime.h>
#include <cuda_fp16.h>
#include <cstdint>

#define D 768
#define DD (768*768)
#define M_ROWS (32*512)
#define L_LAYERS 12
#define NW (L_LAYERS*DD)

typedef __half f16;

// ---------------- scratch (device globals; no allocation allowed) ----------------
__device__ f16 g_xh[M_ROWS*D];
__device__ f16 g_qh[M_ROWS*D];
__device__ f16 g_kh[M_ROWS*D];
__device__ f16 g_vh[M_ROWS*D];
__device__ f16 g_ch[M_ROWS*D];
__device__ f16 g_Wqa_h[NW], g_Wva_h[NW], g_Wk_h[NW], g_Wo_h[NW];
__device__ float g_Lf[24*6144], g_Rf[24*6144];
__device__ float g_pool[32*768];
__device__ int   g_expert;

// ---------------- small helpers ----------------
__device__ __forceinline__ uint32_t pack_h2(float v0, float v1)
{
    __half2 H = __floats2half2_rn(v0, v1);
    return *reinterpret_cast<uint32_t*>(&H);
}

__device__ __forceinline__ void ldm_x4(uint32_t* r, const f16* p)
{
    uint32_t a = (uint32_t)__cvta_generic_to_shared(p);
    asm volatile("ldmatrix.sync.aligned.m8n8.x4.shared.b16 {%0,%1,%2,%3}, [%4];"
        : "=r"(r[0]), "=r"(r[1]), "=r"(r[2]), "=r"(r[3]) : "r"(a));
}
__device__ __forceinline__ void ldm_x4_t(uint32_t* r, const f16* p)
{
    uint32_t a = (uint32_t)__cvta_generic_to_shared(p);
    asm volatile("ldmatrix.sync.aligned.m8n8.x4.trans.shared.b16 {%0,%1,%2,%3}, [%4];"
        : "=r"(r[0]), "=r"(r[1]), "=r"(r[2]), "=r"(r[3]) : "r"(a));
}
__device__ __forceinline__ void mma16816(float* d, const uint32_t* a, uint32_t b0, uint32_t b1)
{
    asm volatile("mma.sync.aligned.m16n8k16.row.col.f32.f16.f16.f32 "
        "{%0,%1,%2,%3}, {%4,%5,%6,%7}, {%8,%9}, {%0,%1,%2,%3};"
        : "+f"(d[0]), "+f"(d[1]), "+f"(d[2]), "+f"(d[3])
        : "r"(a[0]), "r"(a[1]), "r"(a[2]), "r"(a[3]), "r"(b0), "r"(b1));
}
__device__ __forceinline__ void cp16(const f16* smem_dst, const f16* gsrc)
{
    uint32_t s = (uint32_t)__cvta_generic_to_shared(smem_dst);
    asm volatile("cp.async.cg.shared.global [%0], [%1], 16;" :: "r"(s), "l"(gsrc));
}
#define CP_COMMIT() asm volatile("cp.async.commit_group;")
#define CP_WAIT(n)  asm volatile("cp.async.wait_group %0;" :: "n"(n))

// ---------------- router: parallel pooling + finalize ----------------
__global__ void router_pool_kernel(const float* __restrict__ hs)
{
    int tid = threadIdx.x, b = blockIdx.x;
    const float* base = hs + (size_t)31 * 512 * 768 + (size_t)b * 16 * 768;
    float s = 0.f;
    #pragma unroll
    for (int i = 0; i < 16; i++) s += base[(size_t)i * 768 + tid];
    g_pool[b * 768 + tid] = s;
}

__global__ void router_final_kernel(const float* __restrict__ rw)
{
    __shared__ float pooled[768];
    __shared__ float logits[8];
    int tid = threadIdx.x;              // 768 threads
    float s = 0.f;
    #pragma unroll
    for (int p = 0; p < 32; p++) s += g_pool[p * 768 + tid];
    pooled[tid] = s * (1.0f / 512.0f);
    __syncthreads();
    int w = tid >> 5, lane = tid & 31;
    if (w < 8) {
        float p = 0.f;
        for (int d = lane; d < 768; d += 32) p += pooled[d] * rw[d * 8 + w];
        #pragma unroll
        for (int o = 16; o; o >>= 1) p += __shfl_xor_sync(0xffffffffu, p, o);
        if (lane == 0) logits[w] = p;
    }
    __syncthreads();
    if (tid == 0) {
        int best = 0; float bv = logits[0];
        for (int e = 1; e < 8; e++) if (logits[e] > bv) { bv = logits[e]; best = e; }
        g_expert = best;
    }
}

// ---------------- TT factors (Rf stored [o][col], coalesced across threads) ----------------
__global__ void tt_lr_kernel(
    const float* __restrict__ qc0, const float* __restrict__ qc1, const float* __restrict__ qc2,
    const float* __restrict__ qc3, const float* __restrict__ qc4, const float* __restrict__ qc5,
    const float* __restrict__ vc0, const float* __restrict__ vc1, const float* __restrict__ vc2,
    const float* __restrict__ vc3, const float* __restrict__ vc4, const float* __restrict__ vc5)
{
    int l = blockIdx.x, w = blockIdx.y;
    int tid = threadIdx.x;
    int e = g_expert;
    const float* c0p = (w ? vc0 : qc0) + (size_t)(e * 12 + l) * 96;
    const float* c1p = (w ? vc1 : qc1) + (size_t)(e * 12 + l) * 512;
    const float* c2p = (w ? vc2 : qc2) + (size_t)(e * 12 + l) * 512;
    const float* c3p = (w ? vc3 : qc3) + (size_t)(e * 12 + l) * 512;
    const float* c4p = (w ? vc4 : qc4) + (size_t)(e * 12 + l) * 512;
    const float* c5p = (w ? vc5 : qc5) + (size_t)(e * 12 + l) * 96;

    __shared__ float c0[96], c1[512], c2[512], c3[512], c4[512], c5[96];
    __shared__ float T2[768];
    __shared__ float U2[4096];
    for (int i = tid; i < 96; i += 256) { c0[i] = c0p[i]; c5[i] = c5p[i]; }
    for (int i = tid; i < 512; i += 256) {
        c1[i] = c1p[i]; c2[i] = c2p[i]; c3[i] = c3p[i]; c4[i] = c4p[i];
    }
    __syncthreads();

    for (int t = tid; t < 768; t += 256) {
        int j = t >> 6, l2 = (t >> 3) & 7, m = t & 7;
        float s = 0.f;
        #pragma unroll
        for (int k = 0; k < 8; k++) s += c0[j * 8 + k] * c1[((k * 8 + l2) << 3) + m];
        T2[t] = s;
    }
    for (int t = tid; t < 4096; t += 256) {
        int o = t >> 9, p = (t >> 6) & 7, r = (t >> 3) & 7, ss = t & 7;
        float s = 0.f;
        #pragma unroll
        for (int q = 0; q < 8; q++) s += c3[((o * 8 + p) << 3) + q] * c4[((q * 8 + r) << 3) + ss];
        U2[t] = s;
    }
    __syncthreads();

    int chain = w * 12 + l;
    float* lf = g_Lf + (size_t)chain * 6144;
    float* rf = g_Rf + (size_t)chain * 6144;
    for (int t = tid; t < 6144; t += 256) {
        int row = t >> 3, o = t & 7;
        int jl = row >> 3, n = row & 7;
        float s = 0.f;
        #pragma unroll
        for (int m = 0; m < 8; m++) s += T2[(jl << 3) + m] * c2[((m * 8 + n) << 3) + o];
        lf[t] = s;
    }
    // Rf layout [o][col]: rf[o*768 + col]
    for (int t = tid; t < 6144; t += 256) {
        int o = t / 768, col = t - o * 768;
        int p = col / 96; int rem = col - p * 96; int r = rem / 12; int tt = rem - r * 12;
        float s = 0.f;
        #pragma unroll
        for (int ss = 0; ss < 8; ss++) s += U2[(((o * 8 + p) << 3) + r) * 8 + ss] * c5[ss * 12 + tt];
        rf[t] = s;
    }
}

// ---------------- W_a = W + 8 * Lf·Rf, fp16 out, 4 cols/thread (float4 loads) ----------------
__global__ void tt_build_kernel(const float* __restrict__ Wq, const float* __restrict__ Wv)
{
    int l = blockIdx.y, w = blockIdx.z;
    int t4 = blockIdx.x * 256 + threadIdx.x;   // group of 4 elements
    int t = t4 * 4;
    int row = t / 768, col = t - row * 768;    // col multiple of 4
    int chain = w * 12 + l;
    const float* lf = g_Lf + (size_t)chain * 6144 + row * 8;
    const float* rf = g_Rf + (size_t)chain * 6144 + col;
    float lfr[8];
    #pragma unroll
    for (int o = 0; o < 8; o++) lfr[o] = lf[o];
    float a0 = 0.f, a1 = 0.f, a2 = 0.f, a3 = 0.f;
    #pragma unroll
    for (int o = 0; o < 8; o++) {
        float4 r4 = *(const float4*)(rf + o * 768);
        a0 += lfr[o] * r4.x; a1 += lfr[o] * r4.y;
        a2 += lfr[o] * r4.z; a3 += lfr[o] * r4.w;
    }
    const float* W = w ? Wv : Wq;
    float4 w4 = *(const float4*)(W + (size_t)l * DD + t);
    f16* Wh = w ? g_Wva_h : g_Wqa_h;
    uint2 out;
    out.x = pack_h2(w4.x + 8.0f * a0, w4.y + 8.0f * a1);
    out.y = pack_h2(w4.z + 8.0f * a2, w4.w + 8.0f * a3);
    *(uint2*)(Wh + (size_t)l * DD + t) = out;
}

// ---------------- fp32 -> fp16, 8 elements/thread, 3 arrays in one launch ----------------
__global__ void convert3_h8(const float* __restrict__ s0, f16* __restrict__ d0, int n0,
                            const float* __restrict__ s1, f16* __restrict__ d1, int n1,
                            const float* __restrict__ s2, f16* __restrict__ d2, int n2)
{
    const float* s = blockIdx.y == 0 ? s0 : (blockIdx.y == 1 ? s1 : s2);
    f16* h = blockIdx.y == 0 ? d0 : (blockIdx.y == 1 ? d1 : d2);
    int n8 = blockIdx.y == 0 ? n0 : (blockIdx.y == 1 ? n1 : n2);
    int i = blockIdx.x * 256 + threadIdx.x;
    if (i < n8) {
        const float4* sp = (const float4*)s + (size_t)i * 2;
        float4 a = sp[0], b = sp[1];
        uint4 r;
        r.x = pack_h2(a.x, a.y); r.y = pack_h2(a.z, a.w);
        r.z = pack_h2(b.x, b.y); r.w = pack_h2(b.z, b.w);
        ((uint4*)h)[i] = r;
    }
}

// ---------------- GEMM: O = A @ W^T + bias, fp16 1-pass MMA ----------------
// tile 128x128x64, 12 K-stages, 3-stage cp.async pipeline, 1 sync/stage, 2 CTA/SM.
// SMEM: 3 stages x (A 128x72 + B 128x72) f16 = 108 KB.
// rowOff: base row of this launch's batch half.
#define G_STG 9216    // f16 elements per array per stage (128*72)
__global__ __launch_bounds__(256, 2) void gemm_mma(
    const f16* __restrict__ Ah,
    const f16* __restrict__ W0h, const f16* __restrict__ W1h, const f16* __restrict__ W2h,
    const float* __restrict__ bias0, const float* __restrict__ bias1, const float* __restrict__ bias2,
    f16* o0, f16* o1, f16* o2, float scale0, int rowOff)
{
    extern __shared__ f16 sm[];
    f16* sAh = sm;                 // [3][128*72]
    f16* sBh = sm + 3 * G_STG;

    int z = blockIdx.z;
    const f16* Wh = z == 0 ? W0h : (z == 1 ? W1h : W2h);
    const float* bias = z == 0 ? bias0 : (z == 1 ? bias1 : bias2);
    f16* O = z == 0 ? o0 : (z == 1 ? o1 : o2);
    float scl = z == 0 ? scale0 : 1.0f;

    int tid = threadIdx.x;
    int lane = tid & 31, warp = tid >> 5;
    int wm = warp >> 1, wn = warp & 1;
    int bm = rowOff + blockIdx.y * 128, bn = blockIdx.x * 128;

    float acc[2][8][4];
    #pragma unroll
    for (int i = 0; i < 2; i++)
        #pragma unroll
        for (int j = 0; j < 8; j++)
            #pragma unroll
            for (int q = 0; q < 4; q++) acc[i][j][q] = 0.f;

    // one stage = 128 rows x 64 f16 per array; 1024 16B chunks / 256 threads = 4 each
    #define LOAD_STAGE(KT, S)                                                     \
    {                                                                             \
        _Pragma("unroll")                                                         \
        for (int i_ = 0; i_ < 4; i_++) {                                          \
            int c_ = tid + i_ * 256;                                              \
            int row_ = c_ >> 3, seg_ = (c_ & 7) * 8;                              \
            size_t ga_ = (size_t)(bm + row_) * D + (KT) * 64 + seg_;              \
            size_t gb_ = (size_t)(bn + row_) * D + (KT) * 64 + seg_;              \
            int so_ = (S) * G_STG + row_ * 72 + seg_;                             \
            cp16(sAh + so_, Ah + ga_);                                            \
            cp16(sBh + so_, Wh + gb_);                                            \
        }                                                                         \
        CP_COMMIT();                                                              \
    }

    LOAD_STAGE(0, 0)
    LOAD_STAGE(1, 1)

    int s = 0, sl = 2;   // compute buffer, next load buffer
    for (int kt = 0; kt < 12; kt++) {
        if (kt < 11) { CP_WAIT(1); } else { CP_WAIT(0); }
        __syncthreads();
        if (kt < 10) {
            LOAD_STAGE(kt + 2, sl)
            sl = (sl == 2) ? 0 : sl + 1;
        }

        #pragma unroll
        for (int kk = 0; kk < 4; kk++) {
            uint32_t afh[2][4];
            #pragma unroll
            for (int im = 0; im < 2; im++) {
                int r = wm * 32 + im * 16 + (lane & 7) + ((lane >> 3) & 1) * 8;
                int ko = kk * 16 + (lane >> 4) * 8;
                ldm_x4(afh[im], sAh + s * G_STG + r * 72 + ko);
            }
            #pragma unroll
            for (int j2 = 0; j2 < 4; j2++) {
                int nr = wn * 64 + j2 * 16 + (lane & 7) + (lane >> 4) * 8;
                int ko = kk * 16 + ((lane >> 3) & 1) * 8;
                uint32_t bh[4];
                ldm_x4(bh, sBh + s * G_STG + nr * 72 + ko);
                #pragma unroll
                for (int im = 0; im < 2; im++) {
                    mma16816(acc[im][2*j2],   afh[im], bh[0], bh[1]);
                    mma16816(acc[im][2*j2+1], afh[im], bh[2], bh[3]);
                }
            }
        }
        s = (s == 2) ? 0 : s + 1;
    }

    #pragma unroll
    for (int im = 0; im < 2; im++) {
        int row0 = bm + wm * 32 + im * 16 + (lane >> 2);
        #pragma unroll
        for (int j = 0; j < 8; j++) {
            int col = bn + wn * 64 + j * 8 + (lane & 3) * 2;
            float b0v = bias[col], b1v = bias[col + 1];
            *(uint32_t*)(O + (size_t)row0 * D + col) =
                pack_h2((acc[im][j][0] + b0v) * scl, (acc[im][j][1] + b1v) * scl);
            *(uint32_t*)(O + (size_t)(row0 + 8) * D + col) =
                pack_h2((acc[im][j][2] + b0v) * scl, (acc[im][j][3] + b1v) * scl);
        }
    }
}

// ---------------- flash attention, fp16 1-pass MMA, full K/V prefetch ----------------
// grid (4 qtiles, 12 heads, 16 batch) per stream; warp owns 16 q-rows.
// SMEM: Q + K0..K3 + V0..V3 (9 x 128x72 f16 = 162 KB), no buffer reuse.
// Q comes pre-scaled by 1/8 from the projection GEMM. bOff: batch offset.
#define ATT_BUF 9216   // f16 elements per buffer (128*72)
__global__ __launch_bounds__(256) void attn_mma(
    const f16* __restrict__ Qh, const f16* __restrict__ Kh, const f16* __restrict__ Vh,
    f16* __restrict__ Ch, int bOff)
{
    extern __shared__ f16 asm_[];
    f16* sQ = asm_;

    int tid = threadIdx.x, lane = tid & 31, warp = tid >> 5;
    int qt = blockIdx.x, h = blockIdx.y, b = blockIdx.z + bOff;
    int rb = b * 512 + qt * 128;
    int chd = h * 64;

    #define ATT_PREFETCH(SRC, KT, DST)                                            \
    {                                                                             \
        _Pragma("unroll")                                                         \
        for (int i_ = 0; i_ < 4; i_++) {                                          \
            int c_ = tid + i_ * 256;                                              \
            int row_ = c_ >> 3, seg_ = (c_ & 7) * 8;                              \
            size_t g_ = (size_t)(b * 512 + (KT) * 128 + row_) * D + chd + seg_;   \
            cp16((DST) + row_ * 72 + seg_, (SRC) + g_);                           \
        }                                                                         \
        CP_COMMIT();                                                              \
    }

    // group 1: Q
    #pragma unroll
    for (int i = 0; i < 4; i++) {
        int c = tid + i * 256;
        int row = c >> 3, seg = (c & 7) * 8;
        cp16(sQ + row * 72 + seg, Qh + (size_t)(rb + row) * D + chd + seg);
    }
    CP_COMMIT();
    // groups 2..9: K0,V0,K1,V1,K2,V2,K3,V3
    #pragma unroll
    for (int t = 0; t < 4; t++) {
        ATT_PREFETCH(Kh, t, asm_ + (1 + t) * ATT_BUF)
        ATT_PREFETCH(Vh, t, asm_ + (5 + t) * ATT_BUF)
    }

    CP_WAIT(8);            // Q arrived
    __syncthreads();
    uint32_t qf[4][4];
    #pragma unroll
    for (int kc = 0; kc < 4; kc++) {
        int r = warp * 16 + (lane & 7) + ((lane >> 3) & 1) * 8;
        int ko = kc * 16 + (lane >> 4) * 8;
        ldm_x4(qf[kc], sQ + r * 72 + ko);
    }

    float m0 = -1e30f, m1 = -1e30f, l0 = 0.f, l1 = 0.f;
    float oac[8][4];
    #pragma unroll
    for (int j = 0; j < 8; j++)
        #pragma unroll
        for (int q = 0; q < 4; q++) oac[j][q] = 0.f;

    #pragma unroll
    for (int kt = 0; kt < 4; kt++) {
        f16* Kb = asm_ + (1 + kt) * ATT_BUF;
        f16* Vb = asm_ + (5 + kt) * ATT_BUF;

        // K_kt visible  (pending allowed: 7,5,3,1)
        if (kt == 0)      { CP_WAIT(7); }
        else if (kt == 1) { CP_WAIT(5); }
        else if (kt == 2) { CP_WAIT(3); }
        else              { CP_WAIT(1); }
        __syncthreads();

        float sa[16][4];
        #pragma unroll
        for (int j = 0; j < 16; j++)
            #pragma unroll
            for (int q = 0; q < 4; q++) sa[j][q] = 0.f;

        #pragma unroll
        for (int kc = 0; kc < 4; kc++) {
            #pragma unroll
            for (int j2 = 0; j2 < 8; j2++) {
                int nr = j2 * 16 + (lane & 7) + (lane >> 4) * 8;
                int ko = kc * 16 + ((lane >> 3) & 1) * 8;
                uint32_t bh[4];
                ldm_x4(bh, Kb + nr * 72 + ko);
                mma16816(sa[2*j2],   qf[kc], bh[0], bh[1]);
                mma16816(sa[2*j2+1], qf[kc], bh[2], bh[3]);
            }
        }

        // online softmax — Q pre-scaled, so sa already holds scores/8
        float mx0 = -1e30f, mx1 = -1e30f;
        #pragma unroll
        for (int j = 0; j < 16; j++) {
            mx0 = fmaxf(mx0, fmaxf(sa[j][0], sa[j][1]));
            mx1 = fmaxf(mx1, fmaxf(sa[j][2], sa[j][3]));
        }
        mx0 = fmaxf(mx0, __shfl_xor_sync(0xffffffffu, mx0, 1));
        mx0 = fmaxf(mx0, __shfl_xor_sync(0xffffffffu, mx0, 2));
        mx1 = fmaxf(mx1, __shfl_xor_sync(0xffffffffu, mx1, 1));
        mx1 = fmaxf(mx1, __shfl_xor_sync(0xffffffffu, mx1, 2));
        float mn0 = fmaxf(m0, mx0), mn1 = fmaxf(m1, mx1);
        float al0 = __expf(m0 - mn0), al1 = __expf(m1 - mn1);
        m0 = mn0; m1 = mn1;
        float s0 = 0.f, s1 = 0.f;
        #pragma unroll
        for (int j = 0; j < 16; j++) {
            sa[j][0] = __expf(sa[j][0] - mn0); sa[j][1] = __expf(sa[j][1] - mn0);
            sa[j][2] = __expf(sa[j][2] - mn1); sa[j][3] = __expf(sa[j][3] - mn1);
            s0 += sa[j][0] + sa[j][1];
            s1 += sa[j][2] + sa[j][3];
        }
        s0 += __shfl_xor_sync(0xffffffffu, s0, 1); s0 += __shfl_xor_sync(0xffffffffu, s0, 2);
        s1 += __shfl_xor_sync(0xffffffffu, s1, 1); s1 += __shfl_xor_sync(0xffffffffu, s1, 2);
        l0 = l0 * al0 + s0; l1 = l1 * al1 + s1;
        #pragma unroll
        for (int j = 0; j < 8; j++) {
            oac[j][0] *= al0; oac[j][1] *= al0; oac[j][2] *= al1; oac[j][3] *= al1;
        }

        // V_kt visible  (pending allowed: 6,4,2,0)
        if (kt == 0)      { CP_WAIT(6); }
        else if (kt == 1) { CP_WAIT(4); }
        else if (kt == 2) { CP_WAIT(2); }
        else              { CP_WAIT(0); }
        __syncthreads();

        // PV: P packed to fp16 in-register as A-fragments
        #pragma unroll
        for (int kc2 = 0; kc2 < 8; kc2++) {
            uint32_t ah[4];
            ah[0] = pack_h2(sa[2*kc2][0],   sa[2*kc2][1]);
            ah[1] = pack_h2(sa[2*kc2][2],   sa[2*kc2][3]);
            ah[2] = pack_h2(sa[2*kc2+1][0], sa[2*kc2+1][1]);
            ah[3] = pack_h2(sa[2*kc2+1][2], sa[2*kc2+1][3]);
            #pragma unroll
            for (int j2 = 0; j2 < 4; j2++) {
                int kr = kc2 * 16 + (lane & 7) + ((lane >> 3) & 1) * 8;
                int dof = j2 * 16 + (lane >> 4) * 8;
                uint32_t vh[4];
                ldm_x4_t(vh, Vb + kr * 72 + dof);
                mma16816(oac[2*j2],   ah, vh[0], vh[1]);
                mma16816(oac[2*j2+1], ah, vh[2], vh[3]);
            }
        }
        // no trailing sync: buffers are never reused
    }

    float i0 = 1.f / l0, i1 = 1.f / l1;
    int row0 = rb + warp * 16 + (lane >> 2);
    #pragma unroll
    for (int j = 0; j < 8; j++) {
        int col = chd + j * 8 + (lane & 3) * 2;
        *(uint32_t*)(Ch + (size_t)row0 * D + col) = pack_h2(oac[j][0] * i0, oac[j][1] * i0);
        *(uint32_t*)(Ch + (size_t)(row0 + 8) * D + col) = pack_h2(oac[j][2] * i1, oac[j][3] * i1);
    }
}

// ---------------- residual + layernorm, warp-per-row, fp16 residual stream ----------------
// FIRST: residual input from fp32 x32; else from fp16 x16.
// LAST: write fp32 out32 (d_out); else write fp16 oh. rowBase: batch-half row offset.
template<int FIRST, int LAST>
__global__ __launch_bounds__(256) void ln_kernel(
    const float* __restrict__ x32, const f16* __restrict__ x16,
    const f16* __restrict__ o,
    const float* __restrict__ sc, const float* __restrict__ bi,
    float* __restrict__ out32, f16* __restrict__ oh, int rowBase)
{
    int lane = threadIdx.x & 31, warp = threadIdx.x >> 5;
    size_t row = (size_t)rowBase + (size_t)blockIdx.x * 8 + warp;
    const uint2* op = (const uint2*)(o + row * 768);

    float v[24];
    float sum = 0.f;
    #pragma unroll
    for (int j = 0; j < 6; j++) {
        int idx = lane + 32 * j;
        float xv0, xv1, xv2, xv3;
        if (FIRST) {
            float4 xv = ((const float4*)(x32 + row * 768))[idx];
            xv0 = xv.x; xv1 = xv.y; xv2 = xv.z; xv3 = xv.w;
        } else {
            uint2 xv = ((const uint2*)(x16 + row * 768))[idx];
            float2 a = __half22float2(*reinterpret_cast<__half2*>(&xv.x));
            float2 b = __half22float2(*reinterpret_cast<__half2*>(&xv.y));
            xv0 = a.x; xv1 = a.y; xv2 = b.x; xv3 = b.y;
        }
        uint2 ov = op[idx];
        float2 f01 = __half22float2(*reinterpret_cast<__half2*>(&ov.x));
        float2 f23 = __half22float2(*reinterpret_cast<__half2*>(&ov.y));
        v[4*j+0] = xv0 + f01.x; v[4*j+1] = xv1 + f01.y;
        v[4*j+2] = xv2 + f23.x; v[4*j+3] = xv3 + f23.y;
        sum += v[4*j+0] + v[4*j+1] + v[4*j+2] + v[4*j+3];
    }
    #pragma unroll
    for (int s = 16; s; s >>= 1) sum += __shfl_xor_sync(0xffffffffu, sum, s);
    float mu = sum * (1.0f / 768.0f);
    float var = 0.f;
    #pragma unroll
    for (int i = 0; i < 24; i++) { float d = v[i] - mu; var += d * d; }
    #pragma unroll
    for (int s = 16; s; s >>= 1) var += __shfl_xor_sync(0xffffffffu, var, s);
    float rstd = rsqrtf(var * (1.0f / 768.0f) + 1e-12f);

    const float4* scp = (const float4*)sc;
    const float4* bip = (const float4*)bi;
    #pragma unroll
    for (int j = 0; j < 6; j++) {
        int idx = lane + 32 * j;
        float4 s4 = scp[idx], b4 = bip[idx];
        float4 r;
        r.x = (v[4*j+0] - mu) * rstd * s4.x + b4.x;
        r.y = (v[4*j+1] - mu) * rstd * s4.y + b4.y;
        r.z = (v[4*j+2] - mu) * rstd * s4.z + b4.z;
        r.w = (v[4*j+3] - mu) * rstd * s4.w + b4.w;
        if (LAST) {
            ((float4*)(out32 + row * 768))[idx] = r;
        } else {
            uint2 h;
            h.x = pack_h2(r.x, r.y);
            h.y = pack_h2(r.z, r.w);
            ((uint2*)(oh + row * 768))[idx] = h;
        }
    }
}

// ---------------- launch ----------------
extern "C" void kernel_launch(void* const* d_in, const int* in_sizes, int n_in,
                              void* d_out, int out_size)
{
    (void)in_sizes; (void)n_in; (void)out_size;
    const float* hs = (const float*)d_in[0];
    const float* rw = (const float*)d_in[1];
    const float* qc[6], * vc[6];
    for (int i = 0; i < 6; i++) { qc[i] = (const float*)d_in[2 + i]; vc[i] = (const float*)d_in[8 + i]; }
    const float* Wq = (const float*)d_in[14];
    const float* Wk = (const float*)d_in[15];
    const float* Wv = (const float*)d_in[16];
    const float* Wo = (const float*)d_in[17];
    const float* bq = (const float*)d_in[18];
    const float* bk = (const float*)d_in[19];
    const float* bv = (const float*)d_in[20];
    const float* bo = (const float*)d_in[21];
    const float* lns = (const float*)d_in[22];
    const float* lnb = (const float*)d_in[23];

    f16 *xh, *qh, *kh, *vh, *chn;
    f16 *Wqa_h, *Wva_h, *Wk_h, *Wo_h;
    cudaGetSymbolAddress((void**)&xh, g_xh);
    cudaGetSymbolAddress((void**)&qh, g_qh);
    cudaGetSymbolAddress((void**)&kh, g_kh);
    cudaGetSymbolAddress((void**)&vh, g_vh);
    cudaGetSymbolAddress((void**)&chn, g_ch);
    cudaGetSymbolAddress((void**)&Wqa_h, g_Wqa_h);
    cudaGetSymbolAddress((void**)&Wva_h, g_Wva_h);
    cudaGetSymbolAddress((void**)&Wk_h, g_Wk_h);
    cudaGetSymbolAddress((void**)&Wo_h, g_Wo_h);

    const int GEMM_SMEM = 6 * G_STG * 2;      // 108 KB (3 stages x K=64)
    const int ATT_SMEM = 9 * ATT_BUF * 2;     // 162 KB
    cudaFuncSetAttribute(gemm_mma, cudaFuncAttributeMaxDynamicSharedMemorySize, GEMM_SMEM);
    cudaFuncSetAttribute(attn_mma, cudaFuncAttributeMaxDynamicSharedMemorySize, ATT_SMEM);

    // fork/join streams + events: created ONCE (first, eager call) and reused on
    // every subsequent call, so the graph-capture call allocates nothing and the
    // post-teardown memory baseline is unchanged.
    static cudaStream_t s_st0 = nullptr, s_st1 = nullptr;
    static cudaEvent_t s_evRoot = nullptr, s_evA = nullptr, s_evB = nullptr;
    static cudaEvent_t s_evP0 = nullptr, s_evP1 = nullptr;
    if (s_st0 == nullptr) {
        cudaStreamCreateWithFlags(&s_st0, cudaStreamNonBlocking);
        cudaStreamCreateWithFlags(&s_st1, cudaStreamNonBlocking);
        cudaEventCreateWithFlags(&s_evRoot, cudaEventDisableTiming);
        cudaEventCreateWithFlags(&s_evA, cudaEventDisableTiming);
        cudaEventCreateWithFlags(&s_evB, cudaEventDisableTiming);
        cudaEventCreateWithFlags(&s_evP0, cudaEventDisableTiming);
        cudaEventCreateWithFlags(&s_evP1, cudaEventDisableTiming);
    }
    cudaStream_t st[2] = { s_st0, s_st1 };

    // ---- preprocessing: two independent chains, overlapped ----
    cudaEventRecord(s_evRoot, 0);
    cudaStreamWaitEvent(st[0], s_evRoot, 0);
    cudaStreamWaitEvent(st[1], s_evRoot, 0);

    // chain A (st0): router -> tt factors -> adapted Q/V weights
    router_pool_kernel<<<32, 768, 0, st[0]>>>(hs);
    router_final_kernel<<<1, 768, 0, st[0]>>>(rw);
    tt_lr_kernel<<<dim3(12, 2), 256, 0, st[0]>>>(qc[0], qc[1], qc[2], qc[3], qc[4], qc[5],
                                                 vc[0], vc[1], vc[2], vc[3], vc[4], vc[5]);
    tt_build_kernel<<<dim3(DD / 1024, 12, 2), 256, 0, st[0]>>>(Wq, Wv);
    // chain B (st1): fp32->fp16 converts, then layer-0 K projection (needs only
    // xh + Wk_h, both produced by this chain) hidden under chain A's TT work.
    {
        int n0 = NW / 8, n2 = M_ROWS * D / 8;
        int gx = (n2 + 255) / 256;
        convert3_h8<<<dim3(gx, 3), 256, 0, st[1]>>>(Wk, Wk_h, n0, Wo, Wo_h, n0, hs, xh, n2);
    }
    gemm_mma<<<dim3(6, 128, 1), 256, GEMM_SMEM, st[1]>>>(
        xh, Wk_h, Wk_h, Wk_h, bk, bk, bk, kh, kh, kh, 1.0f, 0);
    // cross-join: each stream needs both chains before the layer loop
    cudaEventRecord(s_evP0, st[0]);
    cudaEventRecord(s_evP1, st[1]);
    cudaStreamWaitEvent(st[0], s_evP1, 0);
    cudaStreamWaitEvent(st[1], s_evP0, 0);

    for (int l = 0; l < 12; l++) {
        size_t wo = (size_t)l * DD;
        size_t bofs = (size_t)l * D;

        if (l == 0) {
            // K already projected during preprocessing; only Q and V here.
            for (int hf = 0; hf < 2; hf++) {
                int rowOff = hf * (M_ROWS / 2);
                gemm_mma<<<dim3(6, 64, 2), 256, GEMM_SMEM, st[hf]>>>(
                    xh,
                    Wqa_h + wo, Wva_h + wo, Wva_h + wo,
                    bq + bofs, bv + bofs, bv + bofs,
                    qh, vh, vh, 0.125f, rowOff);
            }
        } else {
            for (int hf = 0; hf < 2; hf++) {
                int rowOff = hf * (M_ROWS / 2);
                gemm_mma<<<dim3(6, 64, 3), 256, GEMM_SMEM, st[hf]>>>(
                    xh,
                    Wqa_h + wo, Wk_h + wo, Wva_h + wo,
                    bq + bofs, bk + bofs, bv + bofs,
                    qh, kh, vh, 0.125f, rowOff);
            }
        }
        for (int hf = 0; hf < 2; hf++) {
            attn_mma<<<dim3(4, 12, 16), 256, ATT_SMEM, st[hf]>>>(qh, kh, vh, chn, hf * 16);
        }
        for (int hf = 0; hf < 2; hf++) {
            int rowOff = hf * (M_ROWS / 2);
            gemm_mma<<<dim3(6, 64, 1), 256, GEMM_SMEM, st[hf]>>>(
                chn,
                Wo_h + wo, Wo_h + wo, Wo_h + wo,
                bo + bofs, bo + bofs, bo + bofs,
                qh, qh, qh, 1.0f, rowOff);
        }
        for (int hf = 0; hf < 2; hf++) {
            int rowBase = hf * (M_ROWS / 2);
            if (l == 0) {
                ln_kernel<1, 0><<<1024, 256, 0, st[hf]>>>(hs, nullptr, qh,
                    lns + bofs, lnb + bofs, nullptr, xh, rowBase);
            } else if (l < 11) {
                ln_kernel<0, 0><<<1024, 256, 0, st[hf]>>>(nullptr, xh, qh,
                    lns + bofs, lnb + bofs, nullptr, xh, rowBase);
            } else {
                ln_kernel<0, 1><<<1024, 256, 0, st[hf]>>>(nullptr, xh, qh,
                    lns + bofs, lnb + bofs, (float*)d_out, nullptr, rowBase);
            }
        }
    }

    // ---- join back onto the capture stream ----
    cudaEventRecord(s_evA, st[0]);
    cudaEventRecord(s_evB, st[1]);
    cudaStreamWaitEvent(0, s_evA, 0);
    cudaStreamWaitEvent(0, s_evB, 0);
}

// round 15
// speedup vs baseline: 1.0015x; 1.0015x over previous
#include <cuda_runtime.h>
#include <cuda_fp16.h>
#include <cstdint>

#define D 768
#define DD (768*768)
#define M_ROWS (32*512)
#define L_LAYERS 12
#define NW (L_LAYERS*DD)

typedef __half f16;

// ---------------- scratch (device globals; no allocation allowed) ----------------
__device__ f16 g_xh[M_ROWS*D];
__device__ f16 g_qh[M_ROWS*D];
__device__ f16 g_kh[M_ROWS*D];
__device__ f16 g_vh[M_ROWS*D];
__device__ f16 g_ch[M_ROWS*D];
__device__ f16 g_Wqa_h[NW], g_Wva_h[NW], g_Wk_h[NW], g_Wo_h[NW];
__device__ float g_Lf[24*6144], g_Rf[24*6144];
__device__ float g_pool[32*768];
__device__ int   g_expert;

// ---------------- small helpers ----------------
__device__ __forceinline__ uint32_t pack_h2(float v0, float v1)
{
    __half2 H = __floats2half2_rn(v0, v1);
    return *reinterpret_cast<uint32_t*>(&H);
}

__device__ __forceinline__ void ldm_x4(uint32_t* r, const f16* p)
{
    uint32_t a = (uint32_t)__cvta_generic_to_shared(p);
    asm volatile("ldmatrix.sync.aligned.m8n8.x4.shared.b16 {%0,%1,%2,%3}, [%4];"
        : "=r"(r[0]), "=r"(r[1]), "=r"(r[2]), "=r"(r[3]) : "r"(a));
}
__device__ __forceinline__ void ldm_x4_t(uint32_t* r, const f16* p)
{
    uint32_t a = (uint32_t)__cvta_generic_to_shared(p);
    asm volatile("ldmatrix.sync.aligned.m8n8.x4.trans.shared.b16 {%0,%1,%2,%3}, [%4];"
        : "=r"(r[0]), "=r"(r[1]), "=r"(r[2]), "=r"(r[3]) : "r"(a));
}
__device__ __forceinline__ void mma16816(float* d, const uint32_t* a, uint32_t b0, uint32_t b1)
{
    asm volatile("mma.sync.aligned.m16n8k16.row.col.f32.f16.f16.f32 "
        "{%0,%1,%2,%3}, {%4,%5,%6,%7}, {%8,%9}, {%0,%1,%2,%3};"
        : "+f"(d[0]), "+f"(d[1]), "+f"(d[2]), "+f"(d[3])
        : "r"(a[0]), "r"(a[1]), "r"(a[2]), "r"(a[3]), "r"(b0), "r"(b1));
}
__device__ __forceinline__ void cp16(const f16* smem_dst, const f16* gsrc)
{
    uint32_t s = (uint32_t)__cvta_generic_to_shared(smem_dst);
    asm volatile("cp.async.cg.shared.global [%0], [%1], 16;" :: "r"(s), "l"(gsrc));
}
#define CP_COMMIT() asm volatile("cp.async.commit_group;")
#define CP_WAIT(n)  asm volatile("cp.async.wait_group %0;" :: "n"(n))

// ---------------- router: parallel pooling + finalize ----------------
__global__ void router_pool_kernel(const float* __restrict__ hs)
{
    int tid = threadIdx.x, b = blockIdx.x;
    const float* base = hs + (size_t)31 * 512 * 768 + (size_t)b * 16 * 768;
    float s = 0.f;
    #pragma unroll
    for (int i = 0; i < 16; i++) s += base[(size_t)i * 768 + tid];
    g_pool[b * 768 + tid] = s;
}

__global__ void router_final_kernel(const float* __restrict__ rw)
{
    __shared__ float pooled[768];
    __shared__ float logits[8];
    int tid = threadIdx.x;              // 768 threads
    float s = 0.f;
    #pragma unroll
    for (int p = 0; p < 32; p++) s += g_pool[p * 768 + tid];
    pooled[tid] = s * (1.0f / 512.0f);
    __syncthreads();
    int w = tid >> 5, lane = tid & 31;
    if (w < 8) {
        float p = 0.f;
        for (int d = lane; d < 768; d += 32) p += pooled[d] * rw[d * 8 + w];
        #pragma unroll
        for (int o = 16; o; o >>= 1) p += __shfl_xor_sync(0xffffffffu, p, o);
        if (lane == 0) logits[w] = p;
    }
    __syncthreads();
    if (tid == 0) {
        int best = 0; float bv = logits[0];
        for (int e = 1; e < 8; e++) if (logits[e] > bv) { bv = logits[e]; best = e; }
        g_expert = best;
    }
}

// ---------------- TT factors (Rf stored [o][col], coalesced across threads) ----------------
__global__ void tt_lr_kernel(
    const float* __restrict__ qc0, const float* __restrict__ qc1, const float* __restrict__ qc2,
    const float* __restrict__ qc3, const float* __restrict__ qc4, const float* __restrict__ qc5,
    const float* __restrict__ vc0, const float* __restrict__ vc1, const float* __restrict__ vc2,
    const float* __restrict__ vc3, const float* __restrict__ vc4, const float* __restrict__ vc5)
{
    int l = blockIdx.x, w = blockIdx.y;
    int tid = threadIdx.x;
    int e = g_expert;
    const float* c0p = (w ? vc0 : qc0) + (size_t)(e * 12 + l) * 96;
    const float* c1p = (w ? vc1 : qc1) + (size_t)(e * 12 + l) * 512;
    const float* c2p = (w ? vc2 : qc2) + (size_t)(e * 12 + l) * 512;
    const float* c3p = (w ? vc3 : qc3) + (size_t)(e * 12 + l) * 512;
    const float* c4p = (w ? vc4 : qc4) + (size_t)(e * 12 + l) * 512;
    const float* c5p = (w ? vc5 : qc5) + (size_t)(e * 12 + l) * 96;

    __shared__ float c0[96], c1[512], c2[512], c3[512], c4[512], c5[96];
    __shared__ float T2[768];
    __shared__ float U2[4096];
    for (int i = tid; i < 96; i += 256) { c0[i] = c0p[i]; c5[i] = c5p[i]; }
    for (int i = tid; i < 512; i += 256) {
        c1[i] = c1p[i]; c2[i] = c2p[i]; c3[i] = c3p[i]; c4[i] = c4p[i];
    }
    __syncthreads();

    for (int t = tid; t < 768; t += 256) {
        int j = t >> 6, l2 = (t >> 3) & 7, m = t & 7;
        float s = 0.f;
        #pragma unroll
        for (int k = 0; k < 8; k++) s += c0[j * 8 + k] * c1[((k * 8 + l2) << 3) + m];
        T2[t] = s;
    }
    for (int t = tid; t < 4096; t += 256) {
        int o = t >> 9, p = (t >> 6) & 7, r = (t >> 3) & 7, ss = t & 7;
        float s = 0.f;
        #pragma unroll
        for (int q = 0; q < 8; q++) s += c3[((o * 8 + p) << 3) + q] * c4[((q * 8 + r) << 3) + ss];
        U2[t] = s;
    }
    __syncthreads();

    int chain = w * 12 + l;
    float* lf = g_Lf + (size_t)chain * 6144;
    float* rf = g_Rf + (size_t)chain * 6144;
    for (int t = tid; t < 6144; t += 256) {
        int row = t >> 3, o = t & 7;
        int jl = row >> 3, n = row & 7;
        float s = 0.f;
        #pragma unroll
        for (int m = 0; m < 8; m++) s += T2[(jl << 3) + m] * c2[((m * 8 + n) << 3) + o];
        lf[t] = s;
    }
    // Rf layout [o][col]: rf[o*768 + col]
    for (int t = tid; t < 6144; t += 256) {
        int o = t / 768, col = t - o * 768;
        int p = col / 96; int rem = col - p * 96; int r = rem / 12; int tt = rem - r * 12;
        float s = 0.f;
        #pragma unroll
        for (int ss = 0; ss < 8; ss++) s += U2[(((o * 8 + p) << 3) + r) * 8 + ss] * c5[ss * 12 + tt];
        rf[t] = s;
    }
}

// ---------------- W_a = W + 8 * Lf·Rf, fp16 out, 4 cols/thread (float4 loads) ----------------
__global__ void tt_build_kernel(const float* __restrict__ Wq, const float* __restrict__ Wv)
{
    int l = blockIdx.y, w = blockIdx.z;
    int t4 = blockIdx.x * 256 + threadIdx.x;   // group of 4 elements
    int t = t4 * 4;
    int row = t / 768, col = t - row * 768;    // col multiple of 4
    int chain = w * 12 + l;
    const float* lf = g_Lf + (size_t)chain * 6144 + row * 8;
    const float* rf = g_Rf + (size_t)chain * 6144 + col;
    float lfr[8];
    #pragma unroll
    for (int o = 0; o < 8; o++) lfr[o] = lf[o];
    float a0 = 0.f, a1 = 0.f, a2 = 0.f, a3 = 0.f;
    #pragma unroll
    for (int o = 0; o < 8; o++) {
        float4 r4 = *(const float4*)(rf + o * 768);
        a0 += lfr[o] * r4.x; a1 += lfr[o] * r4.y;
        a2 += lfr[o] * r4.z; a3 += lfr[o] * r4.w;
    }
    const float* W = w ? Wv : Wq;
    float4 w4 = *(const float4*)(W + (size_t)l * DD + t);
    f16* Wh = w ? g_Wva_h : g_Wqa_h;
    uint2 out;
    out.x = pack_h2(w4.x + 8.0f * a0, w4.y + 8.0f * a1);
    out.y = pack_h2(w4.z + 8.0f * a2, w4.w + 8.0f * a3);
    *(uint2*)(Wh + (size_t)l * DD + t) = out;
}

// ---------------- fp32 -> fp16, 8 elements/thread, 3 arrays in one launch ----------------
__global__ void convert3_h8(const float* __restrict__ s0, f16* __restrict__ d0, int n0,
                            const float* __restrict__ s1, f16* __restrict__ d1, int n1,
                            const float* __restrict__ s2, f16* __restrict__ d2, int n2)
{
    const float* s = blockIdx.y == 0 ? s0 : (blockIdx.y == 1 ? s1 : s2);
    f16* h = blockIdx.y == 0 ? d0 : (blockIdx.y == 1 ? d1 : d2);
    int n8 = blockIdx.y == 0 ? n0 : (blockIdx.y == 1 ? n1 : n2);
    int i = blockIdx.x * 256 + threadIdx.x;
    if (i < n8) {
        const float4* sp = (const float4*)s + (size_t)i * 2;
        float4 a = sp[0], b = sp[1];
        uint4 r;
        r.x = pack_h2(a.x, a.y); r.y = pack_h2(a.z, a.w);
        r.z = pack_h2(b.x, b.y); r.w = pack_h2(b.z, b.w);
        ((uint4*)h)[i] = r;
    }
}

// ---------------- GEMM: O = A @ W^T + bias, fp16 1-pass MMA ----------------
// tile 128x128x64, 12 K-stages, 3-stage cp.async pipeline, 1 sync/stage, 2 CTA/SM.
// SMEM: 3 stages x (A 128x72 + B 128x72) f16 = 108 KB.
// rowOff: base row of this launch's batch half.
#define G_STG 9216    // f16 elements per array per stage (128*72)
__global__ __launch_bounds__(256, 2) void gemm_mma(
    const f16* __restrict__ Ah,
    const f16* __restrict__ W0h, const f16* __restrict__ W1h, const f16* __restrict__ W2h,
    const float* __restrict__ bias0, const float* __restrict__ bias1, const float* __restrict__ bias2,
    f16* o0, f16* o1, f16* o2, float scale0, int rowOff)
{
    extern __shared__ f16 sm[];
    f16* sAh = sm;                 // [3][128*72]
    f16* sBh = sm + 3 * G_STG;

    int z = blockIdx.z;
    const f16* Wh = z == 0 ? W0h : (z == 1 ? W1h : W2h);
    const float* bias = z == 0 ? bias0 : (z == 1 ? bias1 : bias2);
    f16* O = z == 0 ? o0 : (z == 1 ? o1 : o2);
    float scl = z == 0 ? scale0 : 1.0f;

    int tid = threadIdx.x;
    int lane = tid & 31, warp = tid >> 5;
    int wm = warp >> 1, wn = warp & 1;
    int bm = rowOff + blockIdx.y * 128, bn = blockIdx.x * 128;

    float acc[2][8][4];
    #pragma unroll
    for (int i = 0; i < 2; i++)
        #pragma unroll
        for (int j = 0; j < 8; j++)
            #pragma unroll
            for (int q = 0; q < 4; q++) acc[i][j][q] = 0.f;

    // one stage = 128 rows x 64 f16 per array; 1024 16B chunks / 256 threads = 4 each
    #define LOAD_STAGE(KT, S)                                                     \
    {                                                                             \
        _Pragma("unroll")                                                         \
        for (int i_ = 0; i_ < 4; i_++) {                                          \
            int c_ = tid + i_ * 256;                                              \
            int row_ = c_ >> 3, seg_ = (c_ & 7) * 8;                              \
            size_t ga_ = (size_t)(bm + row_) * D + (KT) * 64 + seg_;              \
            size_t gb_ = (size_t)(bn + row_) * D + (KT) * 64 + seg_;              \
            int so_ = (S) * G_STG + row_ * 72 + seg_;                             \
            cp16(sAh + so_, Ah + ga_);                                            \
            cp16(sBh + so_, Wh + gb_);                                            \
        }                                                                         \
        CP_COMMIT();                                                              \
    }

    LOAD_STAGE(0, 0)
    LOAD_STAGE(1, 1)

    int s = 0, sl = 2;   // compute buffer, next load buffer
    for (int kt = 0; kt < 12; kt++) {
        if (kt < 11) { CP_WAIT(1); } else { CP_WAIT(0); }
        __syncthreads();
        if (kt < 10) {
            LOAD_STAGE(kt + 2, sl)
            sl = (sl == 2) ? 0 : sl + 1;
        }

        #pragma unroll
        for (int kk = 0; kk < 4; kk++) {
            uint32_t afh[2][4];
            #pragma unroll
            for (int im = 0; im < 2; im++) {
                int r = wm * 32 + im * 16 + (lane & 7) + ((lane >> 3) & 1) * 8;
                int ko = kk * 16 + (lane >> 4) * 8;
                ldm_x4(afh[im], sAh + s * G_STG + r * 72 + ko);
            }
            #pragma unroll
            for (int j2 = 0; j2 < 4; j2++) {
                int nr = wn * 64 + j2 * 16 + (lane & 7) + (lane >> 4) * 8;
                int ko = kk * 16 + ((lane >> 3) & 1) * 8;
                uint32_t bh[4];
                ldm_x4(bh, sBh + s * G_STG + nr * 72 + ko);
                #pragma unroll
                for (int im = 0; im < 2; im++) {
                    mma16816(acc[im][2*j2],   afh[im], bh[0], bh[1]);
                    mma16816(acc[im][2*j2+1], afh[im], bh[2], bh[3]);
                }
            }
        }
        s = (s == 2) ? 0 : s + 1;
    }

    #pragma unroll
    for (int im = 0; im < 2; im++) {
        int row0 = bm + wm * 32 + im * 16 + (lane >> 2);
        #pragma unroll
        for (int j = 0; j < 8; j++) {
            int col = bn + wn * 64 + j * 8 + (lane & 3) * 2;
            float b0v = bias[col], b1v = bias[col + 1];
            *(uint32_t*)(O + (size_t)row0 * D + col) =
                pack_h2((acc[im][j][0] + b0v) * scl, (acc[im][j][1] + b1v) * scl);
            *(uint32_t*)(O + (size_t)(row0 + 8) * D + col) =
                pack_h2((acc[im][j][2] + b0v) * scl, (acc[im][j][3] + b1v) * scl);
        }
    }
}

// ---------------- flash attention, fp16 1-pass MMA, 6-buffer ring (108 KB) ----------------
// grid (4 qtiles, 12 heads, 16 batch) per stream; warp owns 16 q-rows.
// Buffers (each 128x72 f16 = 18 KB): K ring = buf0,buf1,buf2 (K3 reuses buf0);
// V: V0=buf3, V1=buf4, V2=buf5 (reuses Q staging), V3=buf3. All reuse points are
// protected by existing barriers; math identical to the 162 KB version.
// Q comes pre-scaled by 1/8 from the projection GEMM. bOff: batch offset.
#define ATT_BUF 9216   // f16 elements per buffer (128*72)
__global__ __launch_bounds__(256) void attn_mma(
    const f16* __restrict__ Qh, const f16* __restrict__ Kh, const f16* __restrict__ Vh,
    f16* __restrict__ Ch, int bOff)
{
    extern __shared__ f16 asm_[];

    int tid = threadIdx.x, lane = tid & 31, warp = tid >> 5;
    int qt = blockIdx.x, h = blockIdx.y, b = blockIdx.z + bOff;
    int rb = b * 512 + qt * 128;
    int chd = h * 64;

    #define ATT_PREFETCH(SRC, KT, DST)                                            \
    {                                                                             \
        _Pragma("unroll")                                                         \
        for (int i_ = 0; i_ < 4; i_++) {                                          \
            int c_ = tid + i_ * 256;                                              \
            int row_ = c_ >> 3, seg_ = (c_ & 7) * 8;                              \
            size_t g_ = (size_t)(b * 512 + (KT) * 128 + row_) * D + chd + seg_;   \
            cp16((DST) + row_ * 72 + seg_, (SRC) + g_);                           \
        }                                                                         \
        CP_COMMIT();                                                              \
    }

    f16* buf0 = asm_;
    f16* buf1 = asm_ + ATT_BUF;
    f16* buf2 = asm_ + 2 * ATT_BUF;
    f16* buf3 = asm_ + 3 * ATT_BUF;
    f16* buf4 = asm_ + 4 * ATT_BUF;
    f16* buf5 = asm_ + 5 * ATT_BUF;

    // g1: Q -> buf5
    #pragma unroll
    for (int i = 0; i < 4; i++) {
        int c = tid + i * 256;
        int row = c >> 3, seg = (c & 7) * 8;
        cp16(buf5 + row * 72 + seg, Qh + (size_t)(rb + row) * D + chd + seg);
    }
    CP_COMMIT();
    // g2..g5: K0->buf0, V0->buf3, K1->buf1, V1->buf4
    ATT_PREFETCH(Kh, 0, buf0)
    ATT_PREFETCH(Vh, 0, buf3)
    ATT_PREFETCH(Kh, 1, buf1)
    ATT_PREFETCH(Vh, 1, buf4)

    CP_WAIT(4);            // Q (g1) arrived
    __syncthreads();
    uint32_t qf[4][4];
    #pragma unroll
    for (int kc = 0; kc < 4; kc++) {
        int r = warp * 16 + (lane & 7) + ((lane >> 3) & 1) * 8;
        int ko = kc * 16 + (lane >> 4) * 8;
        ldm_x4(qf[kc], buf5 + r * 72 + ko);
    }
    __syncthreads();       // all warps done reading Q from buf5
    // g6: K2->buf2, g7: V2->buf5 (Q staging now free)
    ATT_PREFETCH(Kh, 2, buf2)
    ATT_PREFETCH(Vh, 2, buf5)

    float m0 = -1e30f, m1 = -1e30f, l0 = 0.f, l1 = 0.f;
    float oac[8][4];
    #pragma unroll
    for (int j = 0; j < 8; j++)
        #pragma unroll
        for (int q = 0; q < 4; q++) oac[j][q] = 0.f;

    #pragma unroll
    for (int kt = 0; kt < 4; kt++) {
        f16* Kb = (kt == 0 || kt == 3) ? buf0 : (kt == 1 ? buf1 : buf2);
        f16* Vb = (kt == 0 || kt == 3) ? buf3 : (kt == 1 ? buf4 : buf5);

        // K_kt visible: issue ledger g1..g9; waitK = {5,4,3,1}
        if (kt == 0)      { CP_WAIT(5); }
        else if (kt == 1) { CP_WAIT(4); }
        else if (kt == 2) { CP_WAIT(3); }
        else              { CP_WAIT(1); }
        __syncthreads();
        // g9: V3->buf3; all warps finished PV(kt0) reads of buf3 at this barrier
        if (kt == 1) ATT_PREFETCH(Vh, 3, buf3)

        float sa[16][4];
        #pragma unroll
        for (int j = 0; j < 16; j++)
            #pragma unroll
            for (int q = 0; q < 4; q++) sa[j][q] = 0.f;

        #pragma unroll
        for (int kc = 0; kc < 4; kc++) {
            #pragma unroll
            for (int j2 = 0; j2 < 8; j2++) {
                int nr = j2 * 16 + (lane & 7) + (lane >> 4) * 8;
                int ko = kc * 16 + ((lane >> 3) & 1) * 8;
                uint32_t bh[4];
                ldm_x4(bh, Kb + nr * 72 + ko);
                mma16816(sa[2*j2],   qf[kc], bh[0], bh[1]);
                mma16816(sa[2*j2+1], qf[kc], bh[2], bh[3]);
            }
        }

        // online softmax — Q pre-scaled, so sa already holds scores/8
        float mx0 = -1e30f, mx1 = -1e30f;
        #pragma unroll
        for (int j = 0; j < 16; j++) {
            mx0 = fmaxf(mx0, fmaxf(sa[j][0], sa[j][1]));
            mx1 = fmaxf(mx1, fmaxf(sa[j][2], sa[j][3]));
        }
        mx0 = fmaxf(mx0, __shfl_xor_sync(0xffffffffu, mx0, 1));
        mx0 = fmaxf(mx0, __shfl_xor_sync(0xffffffffu, mx0, 2));
        mx1 = fmaxf(mx1, __shfl_xor_sync(0xffffffffu, mx1, 1));
        mx1 = fmaxf(mx1, __shfl_xor_sync(0xffffffffu, mx1, 2));
        float mn0 = fmaxf(m0, mx0), mn1 = fmaxf(m1, mx1);
        float al0 = __expf(m0 - mn0), al1 = __expf(m1 - mn1);
        m0 = mn0; m1 = mn1;
        float s0 = 0.f, s1 = 0.f;
        #pragma unroll
        for (int j = 0; j < 16; j++) {
            sa[j][0] = __expf(sa[j][0] - mn0); sa[j][1] = __expf(sa[j][1] - mn0);
            sa[j][2] = __expf(sa[j][2] - mn1); sa[j][3] = __expf(sa[j][3] - mn1);
            s0 += sa[j][0] + sa[j][1];
            s1 += sa[j][2] + sa[j][3];
        }
        s0 += __shfl_xor_sync(0xffffffffu, s0, 1); s0 += __shfl_xor_sync(0xffffffffu, s0, 2);
        s1 += __shfl_xor_sync(0xffffffffu, s1, 1); s1 += __shfl_xor_sync(0xffffffffu, s1, 2);
        l0 = l0 * al0 + s0; l1 = l1 * al1 + s1;
        #pragma unroll
        for (int j = 0; j < 8; j++) {
            oac[j][0] *= al0; oac[j][1] *= al0; oac[j][2] *= al1; oac[j][3] *= al1;
        }

        // V_kt visible: waitV = {4,4,2,0}
        if (kt == 0)      { CP_WAIT(4); }
        else if (kt == 1) { CP_WAIT(4); }
        else if (kt == 2) { CP_WAIT(2); }
        else              { CP_WAIT(0); }
        __syncthreads();
        // g8: K3->buf0; all warps finished QK(kt0) reads of buf0 at this barrier
        if (kt == 0) ATT_PREFETCH(Kh, 3, buf0)

        // PV: P packed to fp16 in-register as A-fragments
        #pragma unroll
        for (int kc2 = 0; kc2 < 8; kc2++) {
            uint32_t ah[4];
            ah[0] = pack_h2(sa[2*kc2][0],   sa[2*kc2][1]);
            ah[1] = pack_h2(sa[2*kc2][2],   sa[2*kc2][3]);
            ah[2] = pack_h2(sa[2*kc2+1][0], sa[2*kc2+1][1]);
            ah[3] = pack_h2(sa[2*kc2+1][2], sa[2*kc2+1][3]);
            #pragma unroll
            for (int j2 = 0; j2 < 4; j2++) {
                int kr = kc2 * 16 + (lane & 7) + ((lane >> 3) & 1) * 8;
                int dof = j2 * 16 + (lane >> 4) * 8;
                uint32_t vh[4];
                ldm_x4_t(vh, Vb + kr * 72 + dof);
                mma16816(oac[2*j2],   ah, vh[0], vh[1]);
                mma16816(oac[2*j2+1], ah, vh[2], vh[3]);
            }
        }
        // buffer reuse is handled by the ring + barriers above
    }

    float i0 = 1.f / l0, i1 = 1.f / l1;
    int row0 = rb + warp * 16 + (lane >> 2);
    #pragma unroll
    for (int j = 0; j < 8; j++) {
        int col = chd + j * 8 + (lane & 3) * 2;
        *(uint32_t*)(Ch + (size_t)row0 * D + col) = pack_h2(oac[j][0] * i0, oac[j][1] * i0);
        *(uint32_t*)(Ch + (size_t)(row0 + 8) * D + col) = pack_h2(oac[j][2] * i1, oac[j][3] * i1);
    }
}

// ---------------- residual + layernorm, warp-per-row, fp16 residual stream ----------------
// FIRST: residual input from fp32 x32; else from fp16 x16.
// LAST: write fp32 out32 (d_out); else write fp16 oh. rowBase: batch-half row offset.
template<int FIRST, int LAST>
__global__ __launch_bounds__(256) void ln_kernel(
    const float* __restrict__ x32, const f16* __restrict__ x16,
    const f16* __restrict__ o,
    const float* __restrict__ sc, const float* __restrict__ bi,
    float* __restrict__ out32, f16* __restrict__ oh, int rowBase)
{
    int lane = threadIdx.x & 31, warp = threadIdx.x >> 5;
    size_t row = (size_t)rowBase + (size_t)blockIdx.x * 8 + warp;
    const uint2* op = (const uint2*)(o + row * 768);

    float v[24];
    float sum = 0.f;
    #pragma unroll
    for (int j = 0; j < 6; j++) {
        int idx = lane + 32 * j;
        float xv0, xv1, xv2, xv3;
        if (FIRST) {
            float4 xv = ((const float4*)(x32 + row * 768))[idx];
            xv0 = xv.x; xv1 = xv.y; xv2 = xv.z; xv3 = xv.w;
        } else {
            uint2 xv = ((const uint2*)(x16 + row * 768))[idx];
            float2 a = __half22float2(*reinterpret_cast<__half2*>(&xv.x));
            float2 b = __half22float2(*reinterpret_cast<__half2*>(&xv.y));
            xv0 = a.x; xv1 = a.y; xv2 = b.x; xv3 = b.y;
        }
        uint2 ov = op[idx];
        float2 f01 = __half22float2(*reinterpret_cast<__half2*>(&ov.x));
        float2 f23 = __half22float2(*reinterpret_cast<__half2*>(&ov.y));
        v[4*j+0] = xv0 + f01.x; v[4*j+1] = xv1 + f01.y;
        v[4*j+2] = xv2 + f23.x; v[4*j+3] = xv3 + f23.y;
        sum += v[4*j+0] + v[4*j+1] + v[4*j+2] + v[4*j+3];
    }
    #pragma unroll
    for (int s = 16; s; s >>= 1) sum += __shfl_xor_sync(0xffffffffu, sum, s);
    float mu = sum * (1.0f / 768.0f);
    float var = 0.f;
    #pragma unroll
    for (int i = 0; i < 24; i++) { float d = v[i] - mu; var += d * d; }
    #pragma unroll
    for (int s = 16; s; s >>= 1) var += __shfl_xor_sync(0xffffffffu, var, s);
    float rstd = rsqrtf(var * (1.0f / 768.0f) + 1e-12f);

    const float4* scp = (const float4*)sc;
    const float4* bip = (const float4*)bi;
    #pragma unroll
    for (int j = 0; j < 6; j++) {
        int idx = lane + 32 * j;
        float4 s4 = scp[idx], b4 = bip[idx];
        float4 r;
        r.x = (v[4*j+0] - mu) * rstd * s4.x + b4.x;
        r.y = (v[4*j+1] - mu) * rstd * s4.y + b4.y;
        r.z = (v[4*j+2] - mu) * rstd * s4.z + b4.z;
        r.w = (v[4*j+3] - mu) * rstd * s4.w + b4.w;
        if (LAST) {
            ((float4*)(out32 + row * 768))[idx] = r;
        } else {
            uint2 h;
            h.x = pack_h2(r.x, r.y);
            h.y = pack_h2(r.z, r.w);
            ((uint2*)(oh + row * 768))[idx] = h;
        }
    }
}

// ---------------- launch ----------------
extern "C" void kernel_launch(void* const* d_in, const int* in_sizes, int n_in,
                              void* d_out, int out_size)
{
    (void)in_sizes; (void)n_in; (void)out_size;
    const float* hs = (const float*)d_in[0];
    const float* rw = (const float*)d_in[1];
    const float* qc[6], * vc[6];
    for (int i = 0; i < 6; i++) { qc[i] = (const float*)d_in[2 + i]; vc[i] = (const float*)d_in[8 + i]; }
    const float* Wq = (const float*)d_in[14];
    const float* Wk = (const float*)d_in[15];
    const float* Wv = (const float*)d_in[16];
    const float* Wo = (const float*)d_in[17];
    const float* bq = (const float*)d_in[18];
    const float* bk = (const float*)d_in[19];
    const float* bv = (const float*)d_in[20];
    const float* bo = (const float*)d_in[21];
    const float* lns = (const float*)d_in[22];
    const float* lnb = (const float*)d_in[23];

    f16 *xh, *qh, *kh, *vh, *chn;
    f16 *Wqa_h, *Wva_h, *Wk_h, *Wo_h;
    cudaGetSymbolAddress((void**)&xh, g_xh);
    cudaGetSymbolAddress((void**)&qh, g_qh);
    cudaGetSymbolAddress((void**)&kh, g_kh);
    cudaGetSymbolAddress((void**)&vh, g_vh);
    cudaGetSymbolAddress((void**)&chn, g_ch);
    cudaGetSymbolAddress((void**)&Wqa_h, g_Wqa_h);
    cudaGetSymbolAddress((void**)&Wva_h, g_Wva_h);
    cudaGetSymbolAddress((void**)&Wk_h, g_Wk_h);
    cudaGetSymbolAddress((void**)&Wo_h, g_Wo_h);

    const int GEMM_SMEM = 6 * G_STG * 2;      // 108 KB (3 stages x K=64)
    const int ATT_SMEM = 6 * ATT_BUF * 2;     // 108 KB (6-buffer ring)
    cudaFuncSetAttribute(gemm_mma, cudaFuncAttributeMaxDynamicSharedMemorySize, GEMM_SMEM);
    cudaFuncSetAttribute(attn_mma, cudaFuncAttributeMaxDynamicSharedMemorySize, ATT_SMEM);

    // fork/join streams + events: created ONCE (first, eager call) and reused on
    // every subsequent call, so the graph-capture call allocates nothing and the
    // post-teardown memory baseline is unchanged.
    static cudaStream_t s_st0 = nullptr, s_st1 = nullptr;
    static cudaEvent_t s_evRoot = nullptr, s_evA = nullptr, s_evB = nullptr;
    static cudaEvent_t s_evP0 = nullptr, s_evP1 = nullptr;
    if (s_st0 == nullptr) {
        cudaStreamCreateWithFlags(&s_st0, cudaStreamNonBlocking);
        cudaStreamCreateWithFlags(&s_st1, cudaStreamNonBlocking);
        cudaEventCreateWithFlags(&s_evRoot, cudaEventDisableTiming);
        cudaEventCreateWithFlags(&s_evA, cudaEventDisableTiming);
        cudaEventCreateWithFlags(&s_evB, cudaEventDisableTiming);
        cudaEventCreateWithFlags(&s_evP0, cudaEventDisableTiming);
        cudaEventCreateWithFlags(&s_evP1, cudaEventDisableTiming);
    }
    cudaStream_t st[2] = { s_st0, s_st1 };

    // ---- preprocessing: two independent chains, overlapped ----
    cudaEventRecord(s_evRoot, 0);
    cudaStreamWaitEvent(st[0], s_evRoot, 0);
    cudaStreamWaitEvent(st[1], s_evRoot, 0);

    // chain A (st0): router -> tt factors -> adapted Q/V weights
    router_pool_kernel<<<32, 768, 0, st[0]>>>(hs);
    router_final_kernel<<<1, 768, 0, st[0]>>>(rw);
    tt_lr_kernel<<<dim3(12, 2), 256, 0, st[0]>>>(qc[0], qc[1], qc[2], qc[3], qc[4], qc[5],
                                                 vc[0], vc[1], vc[2], vc[3], vc[4], vc[5]);
    tt_build_kernel<<<dim3(DD / 1024, 12, 2), 256, 0, st[0]>>>(Wq, Wv);
    // chain B (st1): fp32->fp16 converts, then layer-0 K projection (needs only
    // xh + Wk_h, both produced by this chain) hidden under chain A's TT work.
    {
        int n0 = NW / 8, n2 = M_ROWS * D / 8;
        int gx = (n2 + 255) / 256;
        convert3_h8<<<dim3(gx, 3), 256, 0, st[1]>>>(Wk, Wk_h, n0, Wo, Wo_h, n0, hs, xh, n2);
    }
    gemm_mma<<<dim3(6, 128, 1), 256, GEMM_SMEM, st[1]>>>(
        xh, Wk_h, Wk_h, Wk_h, bk, bk, bk, kh, kh, kh, 1.0f, 0);
    // cross-join: each stream needs both chains before the layer loop
    cudaEventRecord(s_evP0, st[0]);
    cudaEventRecord(s_evP1, st[1]);
    cudaStreamWaitEvent(st[0], s_evP1, 0);
    cudaStreamWaitEvent(st[1], s_evP0, 0);

    for (int l = 0; l < 12; l++) {
        size_t wo = (size_t)l * DD;
        size_t bofs = (size_t)l * D;

        if (l == 0) {
            // K already projected during preprocessing; only Q and V here.
            for (int hf = 0; hf < 2; hf++) {
                int rowOff = hf * (M_ROWS / 2);
                gemm_mma<<<dim3(6, 64, 2), 256, GEMM_SMEM, st[hf]>>>(
                    xh,
                    Wqa_h + wo, Wva_h + wo, Wva_h + wo,
                    bq + bofs, bv + bofs, bv + bofs,
                    qh, vh, vh, 0.125f, rowOff);
            }
        } else {
            for (int hf = 0; hf < 2; hf++) {
                int rowOff = hf * (M_ROWS / 2);
                gemm_mma<<<dim3(6, 64, 3), 256, GEMM_SMEM, st[hf]>>>(
                    xh,
                    Wqa_h + wo, Wk_h + wo, Wva_h + wo,
                    bq + bofs, bk + bofs, bv + bofs,
                    qh, kh, vh, 0.125f, rowOff);
            }
        }
        for (int hf = 0; hf < 2; hf++) {
            attn_mma<<<dim3(4, 12, 16), 256, ATT_SMEM, st[hf]>>>(qh, kh, vh, chn, hf * 16);
        }
        for (int hf = 0; hf < 2; hf++) {
            int rowOff = hf * (M_ROWS / 2);
            gemm_mma<<<dim3(6, 64, 1), 256, GEMM_SMEM, st[hf]>>>(
                chn,
                Wo_h + wo, Wo_h + wo, Wo_h + wo,
                bo + bofs, bo + bofs, bo + bofs,
                qh, qh, qh, 1.0f, rowOff);
        }
        for (int hf = 0; hf < 2; hf++) {
            int rowBase = hf * (M_ROWS / 2);
            if (l == 0) {
                ln_kernel<1, 0><<<1024, 256, 0, st[hf]>>>(hs, nullptr, qh,
                    lns + bofs, lnb + bofs, nullptr, xh, rowBase);
            } else if (l < 11) {
                ln_kernel<0, 0><<<1024, 256, 0, st[hf]>>>(nullptr, xh, qh,
                    lns + bofs, lnb + bofs, nullptr, xh, rowBase);
            } else {
                ln_kernel<0, 1><<<1024, 256, 0, st[hf]>>>(nullptr, xh, qh,
                    lns + bofs, lnb + bofs, (float*)d_out, nullptr, rowBase);
            }
        }
    }

    // ---- join back onto the capture stream ----
    cudaEventRecord(s_evA, st[0]);
    cudaEventRecord(s_evB, st[1]);
    cudaStreamWaitEvent(0, s_evA, 0);
    cudaStreamWaitEvent(0, s_evB, 0);
}

// round 17
// speedup vs baseline: 1.0036x; 1.0021x over previous
#include <cuda_runtime.h>
#include <cuda_fp16.h>
#include <cstdint>

#define D 768
#define DD (768*768)
#define M_ROWS (32*512)
#define L_LAYERS 12
#define NW (L_LAYERS*DD)

typedef __half f16;

// ---------------- scratch (device globals; no allocation allowed) ----------------
__device__ f16 g_xh[M_ROWS*D];
__device__ f16 g_qh[M_ROWS*D];
__device__ f16 g_kh[M_ROWS*D];
__device__ f16 g_vh[M_ROWS*D];
__device__ f16 g_ch[M_ROWS*D];
__device__ f16 g_Wqa_h[NW], g_Wva_h[NW], g_Wk_h[NW], g_Wo_h[NW];
__device__ float g_Lf[24*6144], g_Rf[24*6144];
__device__ float g_pool[32*768];
__device__ int   g_expert;

// ---------------- small helpers ----------------
__device__ __forceinline__ uint32_t pack_h2(float v0, float v1)
{
    __half2 H = __floats2half2_rn(v0, v1);
    return *reinterpret_cast<uint32_t*>(&H);
}

__device__ __forceinline__ void ldm_x4(uint32_t* r, const f16* p)
{
    uint32_t a = (uint32_t)__cvta_generic_to_shared(p);
    asm volatile("ldmatrix.sync.aligned.m8n8.x4.shared.b16 {%0,%1,%2,%3}, [%4];"
        : "=r"(r[0]), "=r"(r[1]), "=r"(r[2]), "=r"(r[3]) : "r"(a));
}
__device__ __forceinline__ void ldm_x4_t(uint32_t* r, const f16* p)
{
    uint32_t a = (uint32_t)__cvta_generic_to_shared(p);
    asm volatile("ldmatrix.sync.aligned.m8n8.x4.trans.shared.b16 {%0,%1,%2,%3}, [%4];"
        : "=r"(r[0]), "=r"(r[1]), "=r"(r[2]), "=r"(r[3]) : "r"(a));
}
__device__ __forceinline__ void mma16816(float* d, const uint32_t* a, uint32_t b0, uint32_t b1)
{
    asm volatile("mma.sync.aligned.m16n8k16.row.col.f32.f16.f16.f32 "
        "{%0,%1,%2,%3}, {%4,%5,%6,%7}, {%8,%9}, {%0,%1,%2,%3};"
        : "+f"(d[0]), "+f"(d[1]), "+f"(d[2]), "+f"(d[3])
        : "r"(a[0]), "r"(a[1]), "r"(a[2]), "r"(a[3]), "r"(b0), "r"(b1));
}
__device__ __forceinline__ void cp16(const f16* smem_dst, const f16* gsrc)
{
    uint32_t s = (uint32_t)__cvta_generic_to_shared(smem_dst);
    asm volatile("cp.async.cg.shared.global [%0], [%1], 16;" :: "r"(s), "l"(gsrc));
}
#define CP_COMMIT() asm volatile("cp.async.commit_group;")
#define CP_WAIT(n)  asm volatile("cp.async.wait_group %0;" :: "n"(n))

// ---------------- router: parallel pooling + finalize ----------------
__global__ void router_pool_kernel(const float* __restrict__ hs)
{
    int tid = threadIdx.x, b = blockIdx.x;
    const float* base = hs + (size_t)31 * 512 * 768 + (size_t)b * 16 * 768;
    float s = 0.f;
    #pragma unroll
    for (int i = 0; i < 16; i++) s += base[(size_t)i * 768 + tid];
    g_pool[b * 768 + tid] = s;
}

__global__ void router_final_kernel(const float* __restrict__ rw)
{
    __shared__ float pooled[768];
    __shared__ float logits[8];
    int tid = threadIdx.x;              // 768 threads
    float s = 0.f;
    #pragma unroll
    for (int p = 0; p < 32; p++) s += g_pool[p * 768 + tid];
    pooled[tid] = s * (1.0f / 512.0f);
    __syncthreads();
    int w = tid >> 5, lane = tid & 31;
    if (w < 8) {
        float p = 0.f;
        for (int d = lane; d < 768; d += 32) p += pooled[d] * rw[d * 8 + w];
        #pragma unroll
        for (int o = 16; o; o >>= 1) p += __shfl_xor_sync(0xffffffffu, p, o);
        if (lane == 0) logits[w] = p;
    }
    __syncthreads();
    if (tid == 0) {
        int best = 0; float bv = logits[0];
        for (int e = 1; e < 8; e++) if (logits[e] > bv) { bv = logits[e]; best = e; }
        g_expert = best;
    }
}

// ---------------- TT factors (Rf stored [o][col], coalesced across threads) ----------------
__global__ void tt_lr_kernel(
    const float* __restrict__ qc0, const float* __restrict__ qc1, const float* __restrict__ qc2,
    const float* __restrict__ qc3, const float* __restrict__ qc4, const float* __restrict__ qc5,
    const float* __restrict__ vc0, const float* __restrict__ vc1, const float* __restrict__ vc2,
    const float* __restrict__ vc3, const float* __restrict__ vc4, const float* __restrict__ vc5)
{
    int l = blockIdx.x, w = blockIdx.y;
    int tid = threadIdx.x;
    int e = g_expert;
    const float* c0p = (w ? vc0 : qc0) + (size_t)(e * 12 + l) * 96;
    const float* c1p = (w ? vc1 : qc1) + (size_t)(e * 12 + l) * 512;
    const float* c2p = (w ? vc2 : qc2) + (size_t)(e * 12 + l) * 512;
    const float* c3p = (w ? vc3 : qc3) + (size_t)(e * 12 + l) * 512;
    const float* c4p = (w ? vc4 : qc4) + (size_t)(e * 12 + l) * 512;
    const float* c5p = (w ? vc5 : qc5) + (size_t)(e * 12 + l) * 96;

    __shared__ float c0[96], c1[512], c2[512], c3[512], c4[512], c5[96];
    __shared__ float T2[768];
    __shared__ float U2[4096];
    for (int i = tid; i < 96; i += 256) { c0[i] = c0p[i]; c5[i] = c5p[i]; }
    for (int i = tid; i < 512; i += 256) {
        c1[i] = c1p[i]; c2[i] = c2p[i]; c3[i] = c3p[i]; c4[i] = c4p[i];
    }
    __syncthreads();

    for (int t = tid; t < 768; t += 256) {
        int j = t >> 6, l2 = (t >> 3) & 7, m = t & 7;
        float s = 0.f;
        #pragma unroll
        for (int k = 0; k < 8; k++) s += c0[j * 8 + k] * c1[((k * 8 + l2) << 3) + m];
        T2[t] = s;
    }
    for (int t = tid; t < 4096; t += 256) {
        int o = t >> 9, p = (t >> 6) & 7, r = (t >> 3) & 7, ss = t & 7;
        float s = 0.f;
        #pragma unroll
        for (int q = 0; q < 8; q++) s += c3[((o * 8 + p) << 3) + q] * c4[((q * 8 + r) << 3) + ss];
        U2[t] = s;
    }
    __syncthreads();

    int chain = w * 12 + l;
    float* lf = g_Lf + (size_t)chain * 6144;
    float* rf = g_Rf + (size_t)chain * 6144;
    for (int t = tid; t < 6144; t += 256) {
        int row = t >> 3, o = t & 7;
        int jl = row >> 3, n = row & 7;
        float s = 0.f;
        #pragma unroll
        for (int m = 0; m < 8; m++) s += T2[(jl << 3) + m] * c2[((m * 8 + n) << 3) + o];
        lf[t] = s;
    }
    // Rf layout [o][col]: rf[o*768 + col]
    for (int t = tid; t < 6144; t += 256) {
        int o = t / 768, col = t - o * 768;
        int p = col / 96; int rem = col - p * 96; int r = rem / 12; int tt = rem - r * 12;
        float s = 0.f;
        #pragma unroll
        for (int ss = 0; ss < 8; ss++) s += U2[(((o * 8 + p) << 3) + r) * 8 + ss] * c5[ss * 12 + tt];
        rf[t] = s;
    }
}

// ---------------- W_a = W + 8 * Lf·Rf, fp16 out, 4 cols/thread (float4 loads) ----------------
__global__ void tt_build_kernel(const float* __restrict__ Wq, const float* __restrict__ Wv)
{
    int l = blockIdx.y, w = blockIdx.z;
    int t4 = blockIdx.x * 256 + threadIdx.x;   // group of 4 elements
    int t = t4 * 4;
    int row = t / 768, col = t - row * 768;    // col multiple of 4
    int chain = w * 12 + l;
    const float* lf = g_Lf + (size_t)chain * 6144 + row * 8;
    const float* rf = g_Rf + (size_t)chain * 6144 + col;
    float lfr[8];
    #pragma unroll
    for (int o = 0; o < 8; o++) lfr[o] = lf[o];
    float a0 = 0.f, a1 = 0.f, a2 = 0.f, a3 = 0.f;
    #pragma unroll
    for (int o = 0; o < 8; o++) {
        float4 r4 = *(const float4*)(rf + o * 768);
        a0 += lfr[o] * r4.x; a1 += lfr[o] * r4.y;
        a2 += lfr[o] * r4.z; a3 += lfr[o] * r4.w;
    }
    const float* W = w ? Wv : Wq;
    float4 w4 = *(const float4*)(W + (size_t)l * DD + t);
    f16* Wh = w ? g_Wva_h : g_Wqa_h;
    uint2 out;
    out.x = pack_h2(w4.x + 8.0f * a0, w4.y + 8.0f * a1);
    out.y = pack_h2(w4.z + 8.0f * a2, w4.w + 8.0f * a3);
    *(uint2*)(Wh + (size_t)l * DD + t) = out;
}

// ---------------- fp32 -> fp16, 8 elements/thread, 3 arrays in one launch ----------------
__global__ void convert3_h8(const float* __restrict__ s0, f16* __restrict__ d0, int n0,
                            const float* __restrict__ s1, f16* __restrict__ d1, int n1,
                            const float* __restrict__ s2, f16* __restrict__ d2, int n2)
{
    const float* s = blockIdx.y == 0 ? s0 : (blockIdx.y == 1 ? s1 : s2);
    f16* h = blockIdx.y == 0 ? d0 : (blockIdx.y == 1 ? d1 : d2);
    int n8 = blockIdx.y == 0 ? n0 : (blockIdx.y == 1 ? n1 : n2);
    int i = blockIdx.x * 256 + threadIdx.x;
    if (i < n8) {
        const float4* sp = (const float4*)s + (size_t)i * 2;
        float4 a = sp[0], b = sp[1];
        uint4 r;
        r.x = pack_h2(a.x, a.y); r.y = pack_h2(a.z, a.w);
        r.z = pack_h2(b.x, b.y); r.w = pack_h2(b.z, b.w);
        ((uint4*)h)[i] = r;
    }
}

// ---------------- GEMM: O = A @ W^T + bias, fp16 1-pass MMA ----------------
// tile 128x128x64, 12 K-stages, 3-stage cp.async pipeline, 1 sync/stage, 2 CTA/SM.
// SMEM: 3 stages x (A 128x72 + B 128x72) f16 = 108 KB.
// rowOff: base row of this launch's batch half.
#define G_STG 9216    // f16 elements per array per stage (128*72)
__global__ __launch_bounds__(256, 2) void gemm_mma(
    const f16* __restrict__ Ah,
    const f16* __restrict__ W0h, const f16* __restrict__ W1h, const f16* __restrict__ W2h,
    const float* __restrict__ bias0, const float* __restrict__ bias1, const float* __restrict__ bias2,
    f16* o0, f16* o1, f16* o2, float scale0, int rowOff)
{
    extern __shared__ f16 sm[];
    f16* sAh = sm;                 // [3][128*72]
    f16* sBh = sm + 3 * G_STG;

    int z = blockIdx.z;
    const f16* Wh = z == 0 ? W0h : (z == 1 ? W1h : W2h);
    const float* bias = z == 0 ? bias0 : (z == 1 ? bias1 : bias2);
    f16* O = z == 0 ? o0 : (z == 1 ? o1 : o2);
    float scl = z == 0 ? scale0 : 1.0f;

    int tid = threadIdx.x;
    int lane = tid & 31, warp = tid >> 5;
    int wm = warp >> 1, wn = warp & 1;
    int bm = rowOff + blockIdx.y * 128, bn = blockIdx.x * 128;

    float acc[2][8][4];
    #pragma unroll
    for (int i = 0; i < 2; i++)
        #pragma unroll
        for (int j = 0; j < 8; j++)
            #pragma unroll
            for (int q = 0; q < 4; q++) acc[i][j][q] = 0.f;

    // one stage = 128 rows x 64 f16 per array; 1024 16B chunks / 256 threads = 4 each
    #define LOAD_STAGE(KT, S)                                                     \
    {                                                                             \
        _Pragma("unroll")                                                         \
        for (int i_ = 0; i_ < 4; i_++) {                                          \
            int c_ = tid + i_ * 256;                                              \
            int row_ = c_ >> 3, seg_ = (c_ & 7) * 8;                              \
            size_t ga_ = (size_t)(bm + row_) * D + (KT) * 64 + seg_;              \
            size_t gb_ = (size_t)(bn + row_) * D + (KT) * 64 + seg_;              \
            int so_ = (S) * G_STG + row_ * 72 + seg_;                             \
            cp16(sAh + so_, Ah + ga_);                                            \
            cp16(sBh + so_, Wh + gb_);                                            \
        }                                                                         \
        CP_COMMIT();                                                              \
    }

    LOAD_STAGE(0, 0)
    LOAD_STAGE(1, 1)

    int s = 0, sl = 2;   // compute buffer, next load buffer
    for (int kt = 0; kt < 12; kt++) {
        if (kt < 11) { CP_WAIT(1); } else { CP_WAIT(0); }
        __syncthreads();
        if (kt < 10) {
            LOAD_STAGE(kt + 2, sl)
            sl = (sl == 2) ? 0 : sl + 1;
        }

        #pragma unroll
        for (int kk = 0; kk < 4; kk++) {
            uint32_t afh[2][4];
            #pragma unroll
            for (int im = 0; im < 2; im++) {
                int r = wm * 32 + im * 16 + (lane & 7) + ((lane >> 3) & 1) * 8;
                int ko = kk * 16 + (lane >> 4) * 8;
                ldm_x4(afh[im], sAh + s * G_STG + r * 72 + ko);
            }
            #pragma unroll
            for (int j2 = 0; j2 < 4; j2++) {
                int nr = wn * 64 + j2 * 16 + (lane & 7) + (lane >> 4) * 8;
                int ko = kk * 16 + ((lane >> 3) & 1) * 8;
                uint32_t bh[4];
                ldm_x4(bh, sBh + s * G_STG + nr * 72 + ko);
                #pragma unroll
                for (int im = 0; im < 2; im++) {
                    mma16816(acc[im][2*j2],   afh[im], bh[0], bh[1]);
                    mma16816(acc[im][2*j2+1], afh[im], bh[2], bh[3]);
                }
            }
        }
        s = (s == 2) ? 0 : s + 1;
    }

    #pragma unroll
    for (int im = 0; im < 2; im++) {
        int row0 = bm + wm * 32 + im * 16 + (lane >> 2);
        #pragma unroll
        for (int j = 0; j < 8; j++) {
            int col = bn + wn * 64 + j * 8 + (lane & 3) * 2;
            float b0v = bias[col], b1v = bias[col + 1];
            *(uint32_t*)(O + (size_t)row0 * D + col) =
                pack_h2((acc[im][j][0] + b0v) * scl, (acc[im][j][1] + b1v) * scl);
            *(uint32_t*)(O + (size_t)(row0 + 8) * D + col) =
                pack_h2((acc[im][j][2] + b0v) * scl, (acc[im][j][3] + b1v) * scl);
        }
    }
}

// ---------------- flash attention, fp16 1-pass MMA, 6-buffer ring (108 KB) ----------------
// grid (4 qtiles, 12 heads, 16 batch) per stream; warp owns 16 q-rows.
// Buffers (each 128x72 f16 = 18 KB): K ring = buf0,buf1,buf2 (K3 reuses buf0);
// V: V0=buf3, V1=buf4, V2=buf5 (reuses Q staging), V3=buf3. All reuse points are
// protected by existing barriers; math identical to the 162 KB version.
// Q comes pre-scaled by 1/8 from the projection GEMM. bOff: batch offset.
#define ATT_BUF 9216   // f16 elements per buffer (128*72)
__global__ __launch_bounds__(256) void attn_mma(
    const f16* __restrict__ Qh, const f16* __restrict__ Kh, const f16* __restrict__ Vh,
    f16* __restrict__ Ch, int bOff)
{
    extern __shared__ f16 asm_[];

    int tid = threadIdx.x, lane = tid & 31, warp = tid >> 5;
    int qt = blockIdx.x, h = blockIdx.y, b = blockIdx.z + bOff;
    int rb = b * 512 + qt * 128;
    int chd = h * 64;

    #define ATT_PREFETCH(SRC, KT, DST)                                            \
    {                                                                             \
        _Pragma("unroll")                                                         \
        for (int i_ = 0; i_ < 4; i_++) {                                          \
            int c_ = tid + i_ * 256;                                              \
            int row_ = c_ >> 3, seg_ = (c_ & 7) * 8;                              \
            size_t g_ = (size_t)(b * 512 + (KT) * 128 + row_) * D + chd + seg_;   \
            cp16((DST) + row_ * 72 + seg_, (SRC) + g_);                           \
        }                                                                         \
        CP_COMMIT();                                                              \
    }

    f16* buf0 = asm_;
    f16* buf1 = asm_ + ATT_BUF;
    f16* buf2 = asm_ + 2 * ATT_BUF;
    f16* buf3 = asm_ + 3 * ATT_BUF;
    f16* buf4 = asm_ + 4 * ATT_BUF;
    f16* buf5 = asm_ + 5 * ATT_BUF;

    // g1: Q -> buf5
    #pragma unroll
    for (int i = 0; i < 4; i++) {
        int c = tid + i * 256;
        int row = c >> 3, seg = (c & 7) * 8;
        cp16(buf5 + row * 72 + seg, Qh + (size_t)(rb + row) * D + chd + seg);
    }
    CP_COMMIT();
    // g2..g5: K0->buf0, V0->buf3, K1->buf1, V1->buf4
    ATT_PREFETCH(Kh, 0, buf0)
    ATT_PREFETCH(Vh, 0, buf3)
    ATT_PREFETCH(Kh, 1, buf1)
    ATT_PREFETCH(Vh, 1, buf4)

    CP_WAIT(4);            // Q (g1) arrived
    __syncthreads();
    uint32_t qf[4][4];
    #pragma unroll
    for (int kc = 0; kc < 4; kc++) {
        int r = warp * 16 + (lane & 7) + ((lane >> 3) & 1) * 8;
        int ko = kc * 16 + (lane >> 4) * 8;
        ldm_x4(qf[kc], buf5 + r * 72 + ko);
    }
    __syncthreads();       // all warps done reading Q from buf5
    // g6: K2->buf2, g7: V2->buf5 (Q staging now free)
    ATT_PREFETCH(Kh, 2, buf2)
    ATT_PREFETCH(Vh, 2, buf5)

    float m0 = -1e30f, m1 = -1e30f, l0 = 0.f, l1 = 0.f;
    float oac[8][4];
    #pragma unroll
    for (int j = 0; j < 8; j++)
        #pragma unroll
        for (int q = 0; q < 4; q++) oac[j][q] = 0.f;

    #pragma unroll
    for (int kt = 0; kt < 4; kt++) {
        f16* Kb = (kt == 0 || kt == 3) ? buf0 : (kt == 1 ? buf1 : buf2);
        f16* Vb = (kt == 0 || kt == 3) ? buf3 : (kt == 1 ? buf4 : buf5);

        // K_kt visible: issue ledger g1..g9; waitK = {5,4,3,1}
        if (kt == 0)      { CP_WAIT(5); }
        else if (kt == 1) { CP_WAIT(4); }
        else if (kt == 2) { CP_WAIT(3); }
        else              { CP_WAIT(1); }
        __syncthreads();
        // g9: V3->buf3; all warps finished PV(kt0) reads of buf3 at this barrier
        if (kt == 1) ATT_PREFETCH(Vh, 3, buf3)

        float sa[16][4];
        #pragma unroll
        for (int j = 0; j < 16; j++)
            #pragma unroll
            for (int q = 0; q < 4; q++) sa[j][q] = 0.f;

        #pragma unroll
        for (int kc = 0; kc < 4; kc++) {
            #pragma unroll
            for (int j2 = 0; j2 < 8; j2++) {
                int nr = j2 * 16 + (lane & 7) + (lane >> 4) * 8;
                int ko = kc * 16 + ((lane >> 3) & 1) * 8;
                uint32_t bh[4];
                ldm_x4(bh, Kb + nr * 72 + ko);
                mma16816(sa[2*j2],   qf[kc], bh[0], bh[1]);
                mma16816(sa[2*j2+1], qf[kc], bh[2], bh[3]);
            }
        }

        // online softmax — Q pre-scaled, so sa already holds scores/8
        float mx0 = -1e30f, mx1 = -1e30f;
        #pragma unroll
        for (int j = 0; j < 16; j++) {
            mx0 = fmaxf(mx0, fmaxf(sa[j][0], sa[j][1]));
            mx1 = fmaxf(mx1, fmaxf(sa[j][2], sa[j][3]));
        }
        mx0 = fmaxf(mx0, __shfl_xor_sync(0xffffffffu, mx0, 1));
        mx0 = fmaxf(mx0, __shfl_xor_sync(0xffffffffu, mx0, 2));
        mx1 = fmaxf(mx1, __shfl_xor_sync(0xffffffffu, mx1, 1));
        mx1 = fmaxf(mx1, __shfl_xor_sync(0xffffffffu, mx1, 2));
        float mn0 = fmaxf(m0, mx0), mn1 = fmaxf(m1, mx1);
        float al0 = __expf(m0 - mn0), al1 = __expf(m1 - mn1);
        m0 = mn0; m1 = mn1;
        float s0 = 0.f, s1 = 0.f;
        #pragma unroll
        for (int j = 0; j < 16; j++) {
            sa[j][0] = __expf(sa[j][0] - mn0); sa[j][1] = __expf(sa[j][1] - mn0);
            sa[j][2] = __expf(sa[j][2] - mn1); sa[j][3] = __expf(sa[j][3] - mn1);
            s0 += sa[j][0] + sa[j][1];
            s1 += sa[j][2] + sa[j][3];
        }
        s0 += __shfl_xor_sync(0xffffffffu, s0, 1); s0 += __shfl_xor_sync(0xffffffffu, s0, 2);
        s1 += __shfl_xor_sync(0xffffffffu, s1, 1); s1 += __shfl_xor_sync(0xffffffffu, s1, 2);
        l0 = l0 * al0 + s0; l1 = l1 * al1 + s1;
        #pragma unroll
        for (int j = 0; j < 8; j++) {
            oac[j][0] *= al0; oac[j][1] *= al0; oac[j][2] *= al1; oac[j][3] *= al1;
        }

        // V_kt visible: waitV = {4,4,2,0}
        if (kt == 0)      { CP_WAIT(4); }
        else if (kt == 1) { CP_WAIT(4); }
        else if (kt == 2) { CP_WAIT(2); }
        else              { CP_WAIT(0); }
        __syncthreads();
        // g8: K3->buf0; all warps finished QK(kt0) reads of buf0 at this barrier
        if (kt == 0) ATT_PREFETCH(Kh, 3, buf0)

        // PV: P packed to fp16 in-register as A-fragments
        #pragma unroll
        for (int kc2 = 0; kc2 < 8; kc2++) {
            uint32_t ah[4];
            ah[0] = pack_h2(sa[2*kc2][0],   sa[2*kc2][1]);
            ah[1] = pack_h2(sa[2*kc2][2],   sa[2*kc2][3]);
            ah[2] = pack_h2(sa[2*kc2+1][0], sa[2*kc2+1][1]);
            ah[3] = pack_h2(sa[2*kc2+1][2], sa[2*kc2+1][3]);
            #pragma unroll
            for (int j2 = 0; j2 < 4; j2++) {
                int kr = kc2 * 16 + (lane & 7) + ((lane >> 3) & 1) * 8;
                int dof = j2 * 16 + (lane >> 4) * 8;
                uint32_t vh[4];
                ldm_x4_t(vh, Vb + kr * 72 + dof);
                mma16816(oac[2*j2],   ah, vh[0], vh[1]);
                mma16816(oac[2*j2+1], ah, vh[2], vh[3]);
            }
        }
        // buffer reuse is handled by the ring + barriers above
    }

    float i0 = 1.f / l0, i1 = 1.f / l1;
    int row0 = rb + warp * 16 + (lane >> 2);
    #pragma unroll
    for (int j = 0; j < 8; j++) {
        int col = chd + j * 8 + (lane & 3) * 2;
        *(uint32_t*)(Ch + (size_t)row0 * D + col) = pack_h2(oac[j][0] * i0, oac[j][1] * i0);
        *(uint32_t*)(Ch + (size_t)(row0 + 8) * D + col) = pack_h2(oac[j][2] * i1, oac[j][3] * i1);
    }
}

// ---------------- residual + layernorm, warp-per-row, fp16 residual stream ----------------
// FIRST: residual input from fp32 x32; else from fp16 x16.
// LAST: write fp32 out32 (d_out); else write fp16 oh. rowBase: batch-half row offset.
template<int FIRST, int LAST>
__global__ __launch_bounds__(256) void ln_kernel(
    const float* __restrict__ x32, const f16* __restrict__ x16,
    const f16* __restrict__ o,
    const float* __restrict__ sc, const float* __restrict__ bi,
    float* __restrict__ out32, f16* __restrict__ oh, int rowBase)
{
    int lane = threadIdx.x & 31, warp = threadIdx.x >> 5;
    size_t row = (size_t)rowBase + (size_t)blockIdx.x * 8 + warp;
    const uint2* op = (const uint2*)(o + row * 768);

    float v[24];
    float sum = 0.f;
    #pragma unroll
    for (int j = 0; j < 6; j++) {
        int idx = lane + 32 * j;
        float xv0, xv1, xv2, xv3;
        if (FIRST) {
            float4 xv = ((const float4*)(x32 + row * 768))[idx];
            xv0 = xv.x; xv1 = xv.y; xv2 = xv.z; xv3 = xv.w;
        } else {
            uint2 xv = ((const uint2*)(x16 + row * 768))[idx];
            float2 a = __half22float2(*reinterpret_cast<__half2*>(&xv.x));
            float2 b = __half22float2(*reinterpret_cast<__half2*>(&xv.y));
            xv0 = a.x; xv1 = a.y; xv2 = b.x; xv3 = b.y;
        }
        uint2 ov = op[idx];
        float2 f01 = __half22float2(*reinterpret_cast<__half2*>(&ov.x));
        float2 f23 = __half22float2(*reinterpret_cast<__half2*>(&ov.y));
        v[4*j+0] = xv0 + f01.x; v[4*j+1] = xv1 + f01.y;
        v[4*j+2] = xv2 + f23.x; v[4*j+3] = xv3 + f23.y;
        sum += v[4*j+0] + v[4*j+1] + v[4*j+2] + v[4*j+3];
    }
    #pragma unroll
    for (int s = 16; s; s >>= 1) sum += __shfl_xor_sync(0xffffffffu, sum, s);
    float mu = sum * (1.0f / 768.0f);
    float var = 0.f;
    #pragma unroll
    for (int i = 0; i < 24; i++) { float d = v[i] - mu; var += d * d; }
    #pragma unroll
    for (int s = 16; s; s >>= 1) var += __shfl_xor_sync(0xffffffffu, var, s);
    float rstd = rsqrtf(var * (1.0f / 768.0f) + 1e-12f);

    const float4* scp = (const float4*)sc;
    const float4* bip = (const float4*)bi;
    #pragma unroll
    for (int j = 0; j < 6; j++) {
        int idx = lane + 32 * j;
        float4 s4 = scp[idx], b4 = bip[idx];
        float4 r;
        r.x = (v[4*j+0] - mu) * rstd * s4.x + b4.x;
        r.y = (v[4*j+1] - mu) * rstd * s4.y + b4.y;
        r.z = (v[4*j+2] - mu) * rstd * s4.z + b4.z;
        r.w = (v[4*j+3] - mu) * rstd * s4.w + b4.w;
        if (LAST) {
            ((float4*)(out32 + row * 768))[idx] = r;
        } else {
            uint2 h;
            h.x = pack_h2(r.x, r.y);
            h.y = pack_h2(r.z, r.w);
            ((uint2*)(oh + row * 768))[idx] = h;
        }
    }
}

// ---------------- launch ----------------
extern "C" void kernel_launch(void* const* d_in, const int* in_sizes, int n_in,
                              void* d_out, int out_size)
{
    (void)in_sizes; (void)n_in; (void)out_size;
    const float* hs = (const float*)d_in[0];
    const float* rw = (const float*)d_in[1];
    const float* qc[6], * vc[6];
    for (int i = 0; i < 6; i++) { qc[i] = (const float*)d_in[2 + i]; vc[i] = (const float*)d_in[8 + i]; }
    const float* Wq = (const float*)d_in[14];
    const float* Wk = (const float*)d_in[15];
    const float* Wv = (const float*)d_in[16];
    const float* Wo = (const float*)d_in[17];
    const float* bq = (const float*)d_in[18];
    const float* bk = (const float*)d_in[19];
    const float* bv = (const float*)d_in[20];
    const float* bo = (const float*)d_in[21];
    const float* lns = (const float*)d_in[22];
    const float* lnb = (const float*)d_in[23];

    f16 *xh, *qh, *kh, *vh, *chn;
    f16 *Wqa_h, *Wva_h, *Wk_h, *Wo_h;
    cudaGetSymbolAddress((void**)&xh, g_xh);
    cudaGetSymbolAddress((void**)&qh, g_qh);
    cudaGetSymbolAddress((void**)&kh, g_kh);
    cudaGetSymbolAddress((void**)&vh, g_vh);
    cudaGetSymbolAddress((void**)&chn, g_ch);
    cudaGetSymbolAddress((void**)&Wqa_h, g_Wqa_h);
    cudaGetSymbolAddress((void**)&Wva_h, g_Wva_h);
    cudaGetSymbolAddress((void**)&Wk_h, g_Wk_h);
    cudaGetSymbolAddress((void**)&Wo_h, g_Wo_h);

    const int GEMM_SMEM = 6 * G_STG * 2;      // 108 KB (3 stages x K=64)
    const int ATT_SMEM = 6 * ATT_BUF * 2;     // 108 KB (6-buffer ring)
    cudaFuncSetAttribute(gemm_mma, cudaFuncAttributeMaxDynamicSharedMemorySize, GEMM_SMEM);
    cudaFuncSetAttribute(attn_mma, cudaFuncAttributeMaxDynamicSharedMemorySize, ATT_SMEM);

    // fork/join streams + events: created ONCE (first, eager call) and reused on
    // every subsequent call, so the graph-capture call allocates nothing and the
    // post-teardown memory baseline is unchanged.
    static cudaStream_t s_st0 = nullptr, s_st1 = nullptr;
    static cudaEvent_t s_evRoot = nullptr, s_evA = nullptr, s_evB = nullptr;
    static cudaEvent_t s_evP0 = nullptr, s_evP1 = nullptr;
    if (s_st0 == nullptr) {
        cudaStreamCreateWithFlags(&s_st0, cudaStreamNonBlocking);
        cudaStreamCreateWithFlags(&s_st1, cudaStreamNonBlocking);
        cudaEventCreateWithFlags(&s_evRoot, cudaEventDisableTiming);
        cudaEventCreateWithFlags(&s_evA, cudaEventDisableTiming);
        cudaEventCreateWithFlags(&s_evB, cudaEventDisableTiming);
        cudaEventCreateWithFlags(&s_evP0, cudaEventDisableTiming);
        cudaEventCreateWithFlags(&s_evP1, cudaEventDisableTiming);
    }
    cudaStream_t st[2] = { s_st0, s_st1 };

    // ---- preprocessing: two independent chains, overlapped ----
    cudaEventRecord(s_evRoot, 0);
    cudaStreamWaitEvent(st[0], s_evRoot, 0);
    cudaStreamWaitEvent(st[1], s_evRoot, 0);

    // chain A (st0): router -> tt factors -> adapted Q/V weights
    router_pool_kernel<<<32, 768, 0, st[0]>>>(hs);
    router_final_kernel<<<1, 768, 0, st[0]>>>(rw);
    tt_lr_kernel<<<dim3(12, 2), 256, 0, st[0]>>>(qc[0], qc[1], qc[2], qc[3], qc[4], qc[5],
                                                 vc[0], vc[1], vc[2], vc[3], vc[4], vc[5]);
    tt_build_kernel<<<dim3(DD / 1024, 12, 2), 256, 0, st[0]>>>(Wq, Wv);
    // chain B (st1): fp32->fp16 converts, then layer-0 K projection (needs only
    // xh + Wk_h, both produced by this chain) hidden under chain A's TT work.
    {
        int n0 = NW / 8, n2 = M_ROWS * D / 8;
        int gx = (n2 + 255) / 256;
        convert3_h8<<<dim3(gx, 3), 256, 0, st[1]>>>(Wk, Wk_h, n0, Wo, Wo_h, n0, hs, xh, n2);
    }
    gemm_mma<<<dim3(6, 128, 1), 256, GEMM_SMEM, st[1]>>>(
        xh, Wk_h, Wk_h, Wk_h, bk, bk, bk, kh, kh, kh, 1.0f, 0);
    // cross-join: each stream needs both chains before the layer loop
    cudaEventRecord(s_evP0, st[0]);
    cudaEventRecord(s_evP1, st[1]);
    cudaStreamWaitEvent(st[0], s_evP1, 0);
    cudaStreamWaitEvent(st[1], s_evP0, 0);

    for (int l = 0; l < 12; l++) {
        size_t wo = (size_t)l * DD;
        size_t bofs = (size_t)l * D;

        if (l == 0) {
            // K already projected during preprocessing; only Q and V here.
            for (int hf = 0; hf < 2; hf++) {
                int rowOff = hf * (M_ROWS / 2);
                gemm_mma<<<dim3(6, 64, 2), 256, GEMM_SMEM, st[hf]>>>(
                    xh,
                    Wqa_h + wo, Wva_h + wo, Wva_h + wo,
                    bq + bofs, bv + bofs, bv + bofs,
                    qh, vh, vh, 0.125f, rowOff);
            }
        } else {
            for (int hf = 0; hf < 2; hf++) {
                int rowOff = hf * (M_ROWS / 2);
                gemm_mma<<<dim3(6, 64, 3), 256, GEMM_SMEM, st[hf]>>>(
                    xh,
                    Wqa_h + wo, Wk_h + wo, Wva_h + wo,
                    bq + bofs, bk + bofs, bv + bofs,
                    qh, kh, vh, 0.125f, rowOff);
            }
        }
        for (int hf = 0; hf < 2; hf++) {
            attn_mma<<<dim3(4, 12, 16), 256, ATT_SMEM, st[hf]>>>(qh, kh, vh, chn, hf * 16);
        }
        for (int hf = 0; hf < 2; hf++) {
            int rowOff = hf * (M_ROWS / 2);
            gemm_mma<<<dim3(6, 64, 1), 256, GEMM_SMEM, st[hf]>>>(
                chn,
                Wo_h + wo, Wo_h + wo, Wo_h + wo,
                bo + bofs, bo + bofs, bo + bofs,
                qh, qh, qh, 1.0f, rowOff);
        }
        for (int hf = 0; hf < 2; hf++) {
            int rowBase = hf * (M_ROWS / 2);
            if (l == 0) {
                ln_kernel<1, 0><<<1024, 256, 0, st[hf]>>>(hs, nullptr, qh,
                    lns + bofs, lnb + bofs, nullptr, xh, rowBase);
            } else if (l < 11) {
                ln_kernel<0, 0><<<1024, 256, 0, st[hf]>>>(nullptr, xh, qh,
                    lns + bofs, lnb + bofs, nullptr, xh, rowBase);
            } else {
                ln_kernel<0, 1><<<1024, 256, 0, st[hf]>>>(nullptr, xh, qh,
                    lns + bofs, lnb + bofs, (float*)d_out, nullptr, rowBase);
            }
        }
    }

    // ---- join back onto the capture stream ----
    cudaEventRecord(s_evA, st[0]);
    cudaEventRecord(s_evB, st[1]);
    cudaStreamWaitEvent(0, s_evA, 0);
    cudaStreamWaitEvent(0, s_evB, 0);
}